// round 13
// baseline (speedup 1.0000x reference)
#include <cuda_runtime.h>
#include <cuda_bf16.h>
#include <cstdint>

#define BATCH 64
#define TT 1024
#define DD 512
#define HH 512
#define J4 2048
#define GRID_R 128        // scan grid (<=148 SMs -> co-resident)

// Scratch (static device memory; no runtime allocation)
__device__ float g_xwt[(size_t)TT * 32 * 64 * 64];    // [t][gu][b][ut][g]   512 MB
__device__ __nv_bfloat16 g_xb_hi[(size_t)BATCH * TT * DD];  // X bf16 hi [m][k]  64 MB
__device__ __nv_bfloat16 g_xb_lo[(size_t)BATCH * TT * DD];  // X bf16 lo [m][k]  64 MB
__device__ __nv_bfloat16 g_wib_hi[(size_t)J4 * DD];   // [n][k] bf16 hi      2 MB
__device__ __nv_bfloat16 g_wib_lo[(size_t)J4 * DD];   // [n][k] bf16 lo      2 MB
__device__ __nv_bfloat16 g_whB_hi[(size_t)32 * 64 * 512];   // [gu][r][k]    2 MB
__device__ __nv_bfloat16 g_whB_lo[(size_t)32 * 64 * 512];   // [gu][r][k]    2 MB
__device__ __nv_bfloat16 g_hb_hi[2][BATCH * HH];      // h bf16 hi, [b][u]
__device__ __nv_bfloat16 g_hb_lo[2][BATCH * HH];      // h bf16 lo, [b][u]
__device__ unsigned g_pflag[4][32 * 32];              // [bq][gu*32] production count

// ---------------------------------------------------------------------------
__device__ __forceinline__ uint32_t smem_u32(const void* p) {
    uint32_t a;
    asm("{ .reg .u64 t; cvta.to.shared.u64 t, %1; cvt.u32.u64 %0, t; }"
        : "=r"(a) : "l"(p));
    return a;
}
#define CP_ASYNC16(dst, src) \
    asm volatile("cp.async.cg.shared.global [%0], [%1], 16;" :: "r"(dst), "l"(src))
#define CP_COMMIT()  asm volatile("cp.async.commit_group;" ::: "memory")
#define CP_WAIT(n)   asm volatile("cp.async.wait_group %0;" :: "n"(n) : "memory")

#define MMA_BF16(d, a0, a1, a2, a3, b0, b1)                                    \
    asm volatile("mma.sync.aligned.m16n8k16.row.col.f32.bf16.bf16.f32 "        \
                 "{%0,%1,%2,%3},{%4,%5,%6,%7},{%8,%9},{%0,%1,%2,%3};"          \
                 : "+f"((d)[0]), "+f"((d)[1]), "+f"((d)[2]), "+f"((d)[3])      \
                 : "r"(a0), "r"(a1), "r"(a2), "r"(a3), "r"(b0), "r"(b1))

__device__ __forceinline__ void st_rel(unsigned* p, unsigned v) {
    asm volatile("st.release.gpu.u32 [%0], %1;" :: "l"(p), "r"(v) : "memory");
}
__device__ __forceinline__ unsigned ld_acq(const unsigned* p) {
    unsigned v;
    asm volatile("ld.acquire.gpu.u32 %0, [%1];" : "=r"(v) : "l"(p) : "memory");
    return v;
}

// ---------------------------------------------------------------------------
__global__ void reset_bar_kernel() {
    ((unsigned*)g_pflag)[blockIdx.x * 256 + threadIdx.x] = 0u;
}

// X fp32 -> bf16 hi/lo split (same [m][k] layout)
__global__ void pack_x_kernel(const float* __restrict__ X) {
    size_t i = (size_t)blockIdx.x * 256 + threadIdx.x;
    float w = X[i];
    __nv_bfloat16 hi = __float2bfloat16(w);
    __nv_bfloat16 lo = __float2bfloat16(w - __bfloat162float(hi));
    g_xb_hi[i] = hi;
    g_xb_lo[i] = lo;
}

// Wi[k][n] -> bf16 hi/lo split, transposed [n][k]
__global__ void pack_wi_kernel(const float* __restrict__ Wi) {
    int i = blockIdx.x * 256 + threadIdx.x;
    int k = i & 511;
    int n = i >> 9;
    float w = Wi[(size_t)k * J4 + n];
    __nv_bfloat16 hi = __float2bfloat16(w);
    __nv_bfloat16 lo = __float2bfloat16(w - __bfloat162float(hi));
    g_wib_hi[i] = hi;
    g_wib_lo[i] = lo;
}

// Wh -> per-unit-group B rows: g_whB[gu][r=ut*4+g][k], gu has 16 units (64 rows)
__global__ void pack_whB_kernel(const float* __restrict__ Wh) {
    int i  = blockIdx.x * 256 + threadIdx.x;     // 1,048,576 total
    int k  = i & 511;
    int r  = (i >> 9) & 63;
    int gu = i >> 15;
    int ut = r >> 2, g = r & 3;
    float w = Wh[(size_t)k * J4 + g * 512 + gu * 16 + ut];
    __nv_bfloat16 hi = __float2bfloat16(w);
    __nv_bfloat16 lo = __float2bfloat16(w - __bfloat162float(hi));
    g_whB_hi[i] = hi;
    g_whB_lo[i] = lo;
}

// ---------------------------------------------------------------------------
// HMMA GEMM, cp.async double-buffered (proven): 128x128xK512 (BK=32), 8 warps.
// ---------------------------------------------------------------------------
#define RSTRIDE 80
#define ARR_SZ (128 * RSTRIDE)     // 10240
#define BUFG_SZ (4 * ARR_SZ)       // 40960
#define SMEM_GEMM (2 * BUFG_SZ)    // 81920

// m = b*1024 + t ; j = g*512 + u  ->  g_xwt[t][gu][b][ut][g]
__device__ __forceinline__ void st_xwt(int m, int j, float v) {
    int b = m >> 10, t = m & 1023, u = j & 511, g = j >> 9;
    int gu = u >> 4, ut = u & 15;
    g_xwt[((((size_t)t * 32 + gu) * 64 + b) * 16 + ut) * 4 + g] = v;
}

__global__ __launch_bounds__(256) void gemm_hmma_kernel(const float* __restrict__ bias)
{
    extern __shared__ __align__(16) char sm[];
    const uint32_t sbase = smem_u32(sm);

    const int nBase = blockIdx.x * 128;
    const int mBase = blockIdx.y * 128;
    const int tid = threadIdx.x;
    const int wid = tid >> 5;
    const int lane = tid & 31;
    const int wm = wid >> 2;
    const int wn = wid & 3;
    const int tig = lane & 3;
    const int grp = lane >> 2;

    float acc[4][4][4];
#pragma unroll
    for (int mt = 0; mt < 4; mt++)
#pragma unroll
        for (int nt = 0; nt < 4; nt++)
#pragma unroll
            for (int q = 0; q < 4; q++) acc[mt][nt][q] = 0.f;

    const int s0 = tid * 2;

#define FILL_CHUNK(buf, ch) do {                                               \
    int k0 = (ch) * 32;                                                        \
    uint32_t db = sbase + (buf) * BUFG_SZ;                                     \
    _Pragma("unroll")                                                          \
    for (int q = 0; q < 2; q++) {                                              \
        int s2 = s0 + q;                                                       \
        int row = s2 >> 2, sg = s2 & 3;                                        \
        uint32_t doff = row * RSTRIDE + sg * 16;                               \
        size_t asrc = ((size_t)(mBase + row) * 512 + k0 + sg * 8) * 2;         \
        size_t bsrc = ((size_t)(nBase + row) * 512 + k0 + sg * 8) * 2;         \
        CP_ASYNC16(db + doff,              (const char*)g_xb_hi + asrc);       \
        CP_ASYNC16(db + ARR_SZ + doff,     (const char*)g_xb_lo + asrc);       \
        CP_ASYNC16(db + 2 * ARR_SZ + doff, (const char*)g_wib_hi + bsrc);      \
        CP_ASYNC16(db + 3 * ARR_SZ + doff, (const char*)g_wib_lo + bsrc);      \
    }                                                                          \
} while (0)

    FILL_CHUNK(0, 0);
    CP_COMMIT();

    for (int ch = 0; ch < 16; ch++) {
        if (ch < 15) {
            FILL_CHUNK((ch + 1) & 1, ch + 1);
            CP_COMMIT();
            CP_WAIT(1);
        } else {
            CP_WAIT(0);
        }
        __syncthreads();

        const char* smAH = sm + (ch & 1) * BUFG_SZ;
        const char* smAL = smAH + ARR_SZ;
        const char* smBH = smAH + 2 * ARR_SZ;
        const char* smBL = smAH + 3 * ARR_SZ;

#pragma unroll
        for (int ks = 0; ks < 2; ks++) {
            const int kb = ks * 16;
            uint32_t bhf[4][2], blf[4][2];
#pragma unroll
            for (int nt = 0; nt < 4; nt++) {
                int row = wn * 32 + nt * 8 + grp;
                int boff = row * RSTRIDE + (kb + tig * 2) * 2;
                bhf[nt][0] = *(uint32_t*)(smBH + boff);
                bhf[nt][1] = *(uint32_t*)(smBH + boff + 16);
                blf[nt][0] = *(uint32_t*)(smBL + boff);
                blf[nt][1] = *(uint32_t*)(smBL + boff + 16);
            }
#pragma unroll
            for (int mt = 0; mt < 4; mt++) {
                int row = wm * 64 + mt * 16 + grp;
                int a0o = row * RSTRIDE + (kb + tig * 2) * 2;
                int a1o = a0o + 8 * RSTRIDE;
                uint32_t ah0 = *(uint32_t*)(smAH + a0o);
                uint32_t ah1 = *(uint32_t*)(smAH + a1o);
                uint32_t ah2 = *(uint32_t*)(smAH + a0o + 16);
                uint32_t ah3 = *(uint32_t*)(smAH + a1o + 16);
                uint32_t al0 = *(uint32_t*)(smAL + a0o);
                uint32_t al1 = *(uint32_t*)(smAL + a1o);
                uint32_t al2 = *(uint32_t*)(smAL + a0o + 16);
                uint32_t al3 = *(uint32_t*)(smAL + a1o + 16);
#pragma unroll
                for (int nt = 0; nt < 4; nt++) {
                    MMA_BF16(acc[mt][nt], ah0, ah1, ah2, ah3, bhf[nt][0], bhf[nt][1]);
                    MMA_BF16(acc[mt][nt], al0, al1, al2, al3, bhf[nt][0], bhf[nt][1]);
                    MMA_BF16(acc[mt][nt], ah0, ah1, ah2, ah3, blf[nt][0], blf[nt][1]);
                }
            }
        }
        __syncthreads();
    }

#pragma unroll
    for (int nt = 0; nt < 4; nt++) {
        int j0 = nBase + wn * 32 + nt * 8 + tig * 2;
        float bb0 = __ldg(&bias[j0]);
        float bb1 = __ldg(&bias[j0 + 1]);
#pragma unroll
        for (int mt = 0; mt < 4; mt++) {
            int m0 = mBase + wm * 64 + mt * 16 + grp;
            st_xwt(m0,     j0,     acc[mt][nt][0] + bb0);
            st_xwt(m0,     j0 + 1, acc[mt][nt][1] + bb1);
            st_xwt(m0 + 8, j0,     acc[mt][nt][2] + bb0);
            st_xwt(m0 + 8, j0 + 1, acc[mt][nt][3] + bb1);
        }
    }
}

// ---------------------------------------------------------------------------
__device__ __forceinline__ float sigf(float x) {
    return 1.0f / (1.0f + __expf(-x));
}
__device__ __forceinline__ float tanhfast(float x) {
    float e = __expf(2.0f * x);
    return 1.0f - 2.0f / (e + 1.0f);
}

// ---------------------------------------------------------------------------
// HMMA persistent scan, warp-specialized overlap:
// 128 blocks = 32 unit-groups x 4 batch-quarters. 512 thr = 16 warps = 8 kq
// pairs (even warp nw=0: loader+MMA rows 0-31; odd warp nw=1: MMA rows 32-63
// + activation). After the sD join, even warps poll next step's 4 producer
// flags + cp.async the next h slice WHILE odd warps do activation + h stores.
// Flag released by odd warps (named bar 9 over the 8 odd warps -> leader
// fence+store), so loaders polling their own block's flag cannot deadlock.
// sD anti-dependence: even sD writes (s+1) <- pair-bar <- odd partner <- bar9
// <- all activation reads of sD(s) done.
// smem: hbuf[2 parities][hi|lo 16x1040B] | sD[8][16][68]f32 | csh[256]
// ---------------------------------------------------------------------------
#define HROW 1040
#define HBUF (16 * HROW)                    // 16,640
#define BUF2 (2 * HBUF)                     // hi+lo for one parity: 33,280
#define SD_OFF (2 * BUF2)                   // 66,560
#define SDS 68
#define CSH_OFF (SD_OFF + 8 * 16 * SDS * 4) // 101,376
#define SMEM_SCAN (CSH_OFF + 1024)          // 102,400

__global__ __launch_bounds__(512, 1) void lstm_scan_kernel(
    const float* __restrict__ c0, const float* __restrict__ h0,
    float* __restrict__ out)
{
    extern __shared__ __align__(16) char sm[];
    float* sD  = (float*)(sm + SD_OFF);
    float* csh = (float*)(sm + CSH_OFF);
    const uint32_t sbase = smem_u32(sm);

    const int bx = blockIdx.x;
    const int gu = bx >> 2;            // unit group 0..31 (16 units)
    const int bq = bx & 3;             // batch quarter 0..3 (16 batches)
    const int u_base = gu * 16;
    const int b_base = bq * 16;
    const int tid = threadIdx.x;
    const int lane = tid & 31;
    const int wid = tid >> 5;
    const int grp = lane >> 2;
    const int tig = lane & 3;
    const int nw = wid & 1;            // 0 = loader+MMA, 1 = MMA+activation
    const int kq = wid >> 1;           // k slice (2x32 units)
    // activation mapping (odd warps only): aidx in [0,256)
    const int aidx = (wid >> 1) * 32 + lane;
    const int ab = aidx >> 4;          // local batch 0..15
    const int au = aidx & 15;          // unit 0..15

    // ---- Wh B fragments -> registers (warp: 32 rows x 64 k) ----
    uint32_t bH[4][4][2], bL[4][4][2];
    {
        const __nv_bfloat16* baseH = g_whB_hi + (size_t)gu * 64 * 512;
        const __nv_bfloat16* baseL = g_whB_lo + (size_t)gu * 64 * 512;
#pragma unroll
        for (int ks = 0; ks < 4; ks++) {
            int kf = (ks < 2) ? (kq * 32 + ks * 16) : (256 + kq * 32 + (ks - 2) * 16);
            kf += tig * 2;
#pragma unroll
            for (int nt = 0; nt < 4; nt++) {
                int r = nw * 32 + nt * 8 + grp;
                bH[ks][nt][0] = *(const uint32_t*)(baseH + (size_t)r * 512 + kf);
                bH[ks][nt][1] = *(const uint32_t*)(baseH + (size_t)r * 512 + kf + 8);
                bL[ks][nt][0] = *(const uint32_t*)(baseL + (size_t)r * 512 + kf);
                bL[ks][nt][1] = *(const uint32_t*)(baseL + (size_t)r * 512 + kf + 8);
            }
        }
    }

    // ---- init c (csh) and h[0] (global, bf16 hi/lo) by odd warps ----
    if (nw == 1) {
        int bg = b_base + ab;
        csh[aidx] = c0[bg * HH + u_base + au];
        float hv = h0[bg * HH + u_base + au];
        __nv_bfloat16 hi = __float2bfloat16(hv);
        __nv_bfloat16 lo = __float2bfloat16(hv - __bfloat162float(hi));
        g_hb_hi[0][bg * HH + u_base + au] = hi;
        g_hb_lo[0][bg * HH + u_base + au] = lo;
    }
    __syncthreads();
    if (tid == 0) {
        __threadfence();
        st_rel(&g_pflag[bq][gu * 32], 1u);    // production #0 (init) done
    }

    // ---- pre-loop: loaders poll flag>=1 and fetch h(step 0, parity 0) ----
    if (nw == 0) {
        if (lane < 4) {
            int pg = 2 * kq + (lane & 1) + ((lane >> 1) << 4);
            const unsigned* f = &g_pflag[bq][pg * 32];
            while (ld_acq(f) < 1u) __nanosleep(20);
        }
        __syncwarp();
        const char* srcH = (const char*)g_hb_hi[0];
        const char* srcL = (const char*)g_hb_lo[0];
#pragma unroll
        for (int q = 0; q < 8; q++) {
            int idx = q * 32 + lane;
            int row = idx & 15;
            int rest = idx >> 4;
            int hl = rest & 1;
            int half = (rest >> 1) & 1;
            int seg = rest >> 2;
            uint32_t off = row * HROW + half * 512 + kq * 64 + seg * 16;
            size_t src = (size_t)(b_base + row) * 1024 + half * 512 + kq * 64 + seg * 16;
            CP_ASYNC16(sbase + hl * HBUF + off, (hl ? srcL : srcH) + src);
        }
        CP_COMMIT();
    }

    float* ys = out + 2 * BATCH * HH;

    for (int s = 0; s < TT; s++) {
        const int ph = s & 1;

        float4 xw = make_float4(0.f, 0.f, 0.f, 0.f);
        if (nw == 1) {
            xw = __ldg((const float4*)g_xwt +
                       ((((size_t)s * 32 + gu) * 64 + b_base + ab) * 16 + au));
        } else {
            CP_WAIT(0);
        }
        // pair barrier: loader's cp.async data visible to partner warp
        asm volatile("bar.sync %0, %1;" :: "r"(kq + 1), "r"(64) : "memory");

        float acc[4][4];   // [nt][q]
#pragma unroll
        for (int nt = 0; nt < 4; nt++)
#pragma unroll
            for (int q = 0; q < 4; q++) acc[nt][q] = 0.f;

        const char* bufH = sm + (s & 1) * BUF2;
        const char* bufL = bufH + HBUF;

#pragma unroll
        for (int ks = 0; ks < 4; ks++) {
            int col = (ks < 2) ? ((kq * 32 + ks * 16 + tig * 2) * 2)
                               : ((256 + kq * 32 + (ks - 2) * 16 + tig * 2) * 2);
            int aoff = grp * HROW + col;
            uint32_t ah0 = *(const uint32_t*)(bufH + aoff);
            uint32_t ah1 = *(const uint32_t*)(bufH + aoff + 8 * HROW);
            uint32_t ah2 = *(const uint32_t*)(bufH + aoff + 16);
            uint32_t ah3 = *(const uint32_t*)(bufH + aoff + 8 * HROW + 16);
            uint32_t al0 = *(const uint32_t*)(bufL + aoff);
            uint32_t al1 = *(const uint32_t*)(bufL + aoff + 8 * HROW);
            uint32_t al2 = *(const uint32_t*)(bufL + aoff + 16);
            uint32_t al3 = *(const uint32_t*)(bufL + aoff + 8 * HROW + 16);
#pragma unroll
            for (int nt = 0; nt < 4; nt++) {
                MMA_BF16(acc[nt], ah0, ah1, ah2, ah3, bH[ks][nt][0], bH[ks][nt][1]);
                MMA_BF16(acc[nt], al0, al1, al2, al3, bH[ks][nt][0], bH[ks][nt][1]);
                MMA_BF16(acc[nt], ah0, ah1, ah2, ah3, bL[ks][nt][0], bL[ks][nt][1]);
            }
        }

        // store D partials: sD[kq][b 16][r 64]
#pragma unroll
        for (int nt = 0; nt < 4; nt++) {
            int r = nw * 32 + nt * 8 + tig * 2;
            *(float2*)&sD[(kq * 16 + grp) * SDS + r] =
                make_float2(acc[nt][0], acc[nt][1]);
            *(float2*)&sD[(kq * 16 + grp + 8) * SDS + r] =
                make_float2(acc[nt][2], acc[nt][3]);
        }
        __syncthreads();   // sD complete

        if (nw == 0) {
            // ---- overlap phase: poll + prefetch h(s+1) during activation ----
            if (s < TT - 1) {
                if (lane < 4) {
                    int pg = 2 * kq + (lane & 1) + ((lane >> 1) << 4);
                    const unsigned* f = &g_pflag[bq][pg * 32];
                    while (ld_acq(f) < (unsigned)(s + 2)) __nanosleep(20);
                }
                __syncwarp();
                const char* srcH = (const char*)g_hb_hi[ph ^ 1];
                const char* srcL = (const char*)g_hb_lo[ph ^ 1];
                uint32_t dbase = sbase + ((s + 1) & 1) * BUF2;
#pragma unroll
                for (int q = 0; q < 8; q++) {
                    int idx = q * 32 + lane;
                    int row = idx & 15;
                    int rest = idx >> 4;
                    int hl = rest & 1;
                    int half = (rest >> 1) & 1;
                    int seg = rest >> 2;
                    uint32_t off = row * HROW + half * 512 + kq * 64 + seg * 16;
                    size_t src = (size_t)(b_base + row) * 1024 + half * 512 + kq * 64 + seg * 16;
                    CP_ASYNC16(dbase + hl * HBUF + off, (hl ? srcL : srcH) + src);
                }
                CP_COMMIT();
            }
        } else {
            // ---- activation (odd warps) ----
            float si = xw.x, sf = xw.y, sg2 = xw.z, so = xw.w;
#pragma unroll
            for (int q = 0; q < 8; q++) {
                float4 s4 = *(float4*)&sD[(q * 16 + ab) * SDS + au * 4];
                si += s4.x; sf += s4.y; sg2 += s4.z; so += s4.w;
            }
            float ig = sigf(si);
            float fg = sigf(sf);
            float gg = tanhfast(sg2);
            float og = sigf(so);
            float cold = csh[aidx];
            float cnew = fg * cold + ig * gg;
            float hnew = og * tanhfast(cnew);
            csh[aidx] = cnew;

            int bg = b_base + ab;
            __nv_bfloat16 hi = __float2bfloat16(hnew);
            __nv_bfloat16 lo = __float2bfloat16(hnew - __bfloat162float(hi));
            int uo = bg * HH + u_base + au;
            g_hb_hi[ph ^ 1][uo] = hi;
            g_hb_lo[ph ^ 1][uo] = lo;

            ys[((size_t)bg * TT + s) * HH + u_base + au] = hnew;
            if (s == TT - 1) {
                out[bg * HH + u_base + au] = cnew;                 // cT
                out[BATCH * HH + bg * HH + u_base + au] = hnew;    // hT
            }

            if (s < TT - 1) {
                // join odd warps, then release production flag
                asm volatile("bar.sync 9, 256;" ::: "memory");
                if (wid == 1 && lane == 0) {
                    __threadfence();
                    st_rel(&g_pflag[bq][gu * 32], (unsigned)(s + 2));
                }
            }
        }
    }
}

// ---------------------------------------------------------------------------
extern "C" void kernel_launch(void* const* d_in, const int* in_sizes, int n_in,
                              void* d_out, int out_size) {
    const float* x    = (const float*)d_in[0];   // [64][1024][512]
    const float* c0   = (const float*)d_in[1];   // [64][512]
    const float* h0   = (const float*)d_in[2];   // [64][512]
    const float* Wi   = (const float*)d_in[3];   // [512][2048]
    const float* Wh   = (const float*)d_in[4];   // [512][2048]
    const float* bias = (const float*)d_in[5];   // [2048]
    float* out = (float*)d_out;                  // cT | hT | ys

    cudaFuncSetAttribute(lstm_scan_kernel,
                         cudaFuncAttributeMaxDynamicSharedMemorySize, SMEM_SCAN);
    cudaFuncSetAttribute(gemm_hmma_kernel,
                         cudaFuncAttributeMaxDynamicSharedMemorySize, SMEM_GEMM);

    pack_x_kernel<<<131072, 256>>>(x);
    pack_wi_kernel<<<4096, 256>>>(Wi);
    pack_whB_kernel<<<4096, 256>>>(Wh);
    reset_bar_kernel<<<16, 256>>>();
    gemm_hmma_kernel<<<dim3(16, 512), 256, SMEM_GEMM>>>(bias);
    lstm_scan_kernel<<<GRID_R, 512, SMEM_SCAN>>>(c0, h0, out);
}

// round 14
// speedup vs baseline: 1.0326x; 1.0326x over previous
#include <cuda_runtime.h>
#include <cuda_bf16.h>
#include <cstdint>

#define BATCH 64
#define TT 1024
#define DD 512
#define HH 512
#define J4 2048
#define GRID_R 128        // scan grid (<=148 SMs -> co-resident)

// Scratch (static device memory; no runtime allocation)
__device__ float g_xwt[(size_t)TT * 32 * 64 * 64];    // [t][gu][b][ut][g]   512 MB
__device__ __nv_bfloat16 g_xb_hi[(size_t)BATCH * TT * DD];  // X bf16 hi [m][k]  64 MB
__device__ __nv_bfloat16 g_xb_lo[(size_t)BATCH * TT * DD];  // X bf16 lo [m][k]  64 MB
__device__ __nv_bfloat16 g_wib_hi[(size_t)J4 * DD];   // [n][k] bf16 hi      2 MB
__device__ __nv_bfloat16 g_wib_lo[(size_t)J4 * DD];   // [n][k] bf16 lo      2 MB
__device__ __nv_bfloat16 g_whB_hi[(size_t)32 * 64 * 512];   // [gu][r][k]    2 MB
__device__ __nv_bfloat16 g_whB_lo[(size_t)32 * 64 * 512];   // [gu][r][k]    2 MB
__device__ __nv_bfloat16 g_hb_hi[2][BATCH * HH];      // h bf16 hi, [b][u]
__device__ __nv_bfloat16 g_hb_lo[2][BATCH * HH];      // h bf16 lo, [b][u]
__device__ unsigned g_pflag[4][32 * 32];              // [bq][gu*32] production count

// ---------------------------------------------------------------------------
__device__ __forceinline__ uint32_t smem_u32(const void* p) {
    uint32_t a;
    asm("{ .reg .u64 t; cvta.to.shared.u64 t, %1; cvt.u32.u64 %0, t; }"
        : "=r"(a) : "l"(p));
    return a;
}
#define CP_ASYNC16(dst, src) \
    asm volatile("cp.async.cg.shared.global [%0], [%1], 16;" :: "r"(dst), "l"(src))
#define CP_COMMIT()  asm volatile("cp.async.commit_group;" ::: "memory")
#define CP_WAIT(n)   asm volatile("cp.async.wait_group %0;" :: "n"(n) : "memory")

#define MMA_BF16(d, a0, a1, a2, a3, b0, b1)                                    \
    asm volatile("mma.sync.aligned.m16n8k16.row.col.f32.bf16.bf16.f32 "        \
                 "{%0,%1,%2,%3},{%4,%5,%6,%7},{%8,%9},{%0,%1,%2,%3};"          \
                 : "+f"((d)[0]), "+f"((d)[1]), "+f"((d)[2]), "+f"((d)[3])      \
                 : "r"(a0), "r"(a1), "r"(a2), "r"(a3), "r"(b0), "r"(b1))

#define LDSM_X4(r0, r1, r2, r3, addr)                                          \
    asm volatile("ldmatrix.sync.aligned.m8n8.x4.shared.b16 {%0,%1,%2,%3}, [%4];" \
                 : "=r"(r0), "=r"(r1), "=r"(r2), "=r"(r3) : "r"(addr))

__device__ __forceinline__ void st_rel(unsigned* p, unsigned v) {
    asm volatile("st.release.gpu.u32 [%0], %1;" :: "l"(p), "r"(v) : "memory");
}
__device__ __forceinline__ unsigned ld_acq(const unsigned* p) {
    unsigned v;
    asm volatile("ld.acquire.gpu.u32 %0, [%1];" : "=r"(v) : "l"(p) : "memory");
    return v;
}

// ---------------------------------------------------------------------------
__global__ void reset_bar_kernel() {
    ((unsigned*)g_pflag)[blockIdx.x * 256 + threadIdx.x] = 0u;
}

// X fp32 -> bf16 hi/lo split (same [m][k] layout)
__global__ void pack_x_kernel(const float* __restrict__ X) {
    size_t i = (size_t)blockIdx.x * 256 + threadIdx.x;
    float w = X[i];
    __nv_bfloat16 hi = __float2bfloat16(w);
    __nv_bfloat16 lo = __float2bfloat16(w - __bfloat162float(hi));
    g_xb_hi[i] = hi;
    g_xb_lo[i] = lo;
}

// Wi[k][n] -> bf16 hi/lo split, transposed [n][k]
__global__ void pack_wi_kernel(const float* __restrict__ Wi) {
    int i = blockIdx.x * 256 + threadIdx.x;
    int k = i & 511;
    int n = i >> 9;
    float w = Wi[(size_t)k * J4 + n];
    __nv_bfloat16 hi = __float2bfloat16(w);
    __nv_bfloat16 lo = __float2bfloat16(w - __bfloat162float(hi));
    g_wib_hi[i] = hi;
    g_wib_lo[i] = lo;
}

// Wh -> per-unit-group B rows: g_whB[gu][r=ut*4+g][k], gu has 16 units (64 rows)
__global__ void pack_whB_kernel(const float* __restrict__ Wh) {
    int i  = blockIdx.x * 256 + threadIdx.x;     // 1,048,576 total
    int k  = i & 511;
    int r  = (i >> 9) & 63;
    int gu = i >> 15;
    int ut = r >> 2, g = r & 3;
    float w = Wh[(size_t)k * J4 + g * 512 + gu * 16 + ut];
    __nv_bfloat16 hi = __float2bfloat16(w);
    __nv_bfloat16 lo = __float2bfloat16(w - __bfloat162float(hi));
    g_whB_hi[i] = hi;
    g_whB_lo[i] = lo;
}

// ---------------------------------------------------------------------------
// HMMA GEMM, cp.async double-buffered + LDSM fragment loads.
// 128x128xK512 (BK=32), 8 warps (2 wm x 4 wn), warp tile 64x32.
// ---------------------------------------------------------------------------
#define RSTRIDE 80
#define ARR_SZ (128 * RSTRIDE)     // 10240
#define BUFG_SZ (4 * ARR_SZ)       // 40960
#define SMEM_GEMM (2 * BUFG_SZ)    // 81920

// m = b*1024 + t ; j = g*512 + u  ->  g_xwt[t][gu][b][ut][g]
__device__ __forceinline__ void st_xwt(int m, int j, float v) {
    int b = m >> 10, t = m & 1023, u = j & 511, g = j >> 9;
    int gu = u >> 4, ut = u & 15;
    g_xwt[((((size_t)t * 32 + gu) * 64 + b) * 16 + ut) * 4 + g] = v;
}

__global__ __launch_bounds__(256) void gemm_hmma_kernel(const float* __restrict__ bias)
{
    extern __shared__ __align__(16) char sm[];
    const uint32_t sbase = smem_u32(sm);

    const int nBase = blockIdx.x * 128;
    const int mBase = blockIdx.y * 128;
    const int tid = threadIdx.x;
    const int wid = tid >> 5;
    const int lane = tid & 31;
    const int wm = wid >> 2;
    const int wn = wid & 3;
    const int tig = lane & 3;
    const int grp = lane >> 2;

    // ldmatrix lane->address mappings
    const int lA = lane & 15;             // A row within 16-row tile
    const int cA = (lane >> 4) * 16;      // A col byte offset (k half)
    const int lB = lane & 7;              // B row within 8-row n-tile
    const int sB = ((lane >> 3) & 1) * 16;// B col byte offset (k half)
    const int nB = lane >> 4;             // B n-tile select within pair

    float acc[4][4][4];
#pragma unroll
    for (int mt = 0; mt < 4; mt++)
#pragma unroll
        for (int nt = 0; nt < 4; nt++)
#pragma unroll
            for (int q = 0; q < 4; q++) acc[mt][nt][q] = 0.f;

    const int s0 = tid * 2;

#define FILL_CHUNK(buf, ch) do {                                               \
    int k0 = (ch) * 32;                                                        \
    uint32_t db = sbase + (buf) * BUFG_SZ;                                     \
    _Pragma("unroll")                                                          \
    for (int q = 0; q < 2; q++) {                                              \
        int s2 = s0 + q;                                                       \
        int row = s2 >> 2, sg = s2 & 3;                                        \
        uint32_t doff = row * RSTRIDE + sg * 16;                               \
        size_t asrc = ((size_t)(mBase + row) * 512 + k0 + sg * 8) * 2;         \
        size_t bsrc = ((size_t)(nBase + row) * 512 + k0 + sg * 8) * 2;         \
        CP_ASYNC16(db + doff,              (const char*)g_xb_hi + asrc);       \
        CP_ASYNC16(db + ARR_SZ + doff,     (const char*)g_xb_lo + asrc);       \
        CP_ASYNC16(db + 2 * ARR_SZ + doff, (const char*)g_wib_hi + bsrc);      \
        CP_ASYNC16(db + 3 * ARR_SZ + doff, (const char*)g_wib_lo + bsrc);      \
    }                                                                          \
} while (0)

    FILL_CHUNK(0, 0);
    CP_COMMIT();

    for (int ch = 0; ch < 16; ch++) {
        if (ch < 15) {
            FILL_CHUNK((ch + 1) & 1, ch + 1);
            CP_COMMIT();
            CP_WAIT(1);
        } else {
            CP_WAIT(0);
        }
        __syncthreads();

        const uint32_t aBase = sbase + (ch & 1) * BUFG_SZ;   // AH base
        const uint32_t aBaseL = aBase + ARR_SZ;              // AL
        const uint32_t bBaseH = aBase + 2 * ARR_SZ;          // BH
        const uint32_t bBaseL = aBase + 3 * ARR_SZ;          // BL

#pragma unroll
        for (int ks = 0; ks < 2; ks++) {
            const int kb2 = ks * 32;   // byte offset of this k-half (16 elem * 2B)
            uint32_t bhf[4][2], blf[4][2];
            // B fragments: 2 n-tiles per ldmatrix.x4
#pragma unroll
            for (int ntp = 0; ntp < 2; ntp++) {
                int rowB = wn * 32 + (ntp * 2 + nB) * 8 + lB;
                uint32_t baddr = rowB * RSTRIDE + kb2 + sB;
                LDSM_X4(bhf[ntp * 2][0], bhf[ntp * 2][1],
                        bhf[ntp * 2 + 1][0], bhf[ntp * 2 + 1][1], bBaseH + baddr);
                LDSM_X4(blf[ntp * 2][0], blf[ntp * 2][1],
                        blf[ntp * 2 + 1][0], blf[ntp * 2 + 1][1], bBaseL + baddr);
            }
#pragma unroll
            for (int mt = 0; mt < 4; mt++) {
                int rowA = wm * 64 + mt * 16 + lA;
                uint32_t aaddr = rowA * RSTRIDE + kb2 + cA;
                uint32_t ah0, ah1, ah2, ah3, al0, al1, al2, al3;
                LDSM_X4(ah0, ah1, ah2, ah3, aBase + aaddr);
                LDSM_X4(al0, al1, al2, al3, aBaseL + aaddr);
#pragma unroll
                for (int nt = 0; nt < 4; nt++) {
                    MMA_BF16(acc[mt][nt], ah0, ah1, ah2, ah3, bhf[nt][0], bhf[nt][1]);
                    MMA_BF16(acc[mt][nt], al0, al1, al2, al3, bhf[nt][0], bhf[nt][1]);
                    MMA_BF16(acc[mt][nt], ah0, ah1, ah2, ah3, blf[nt][0], blf[nt][1]);
                }
            }
        }
        __syncthreads();
    }

#pragma unroll
    for (int nt = 0; nt < 4; nt++) {
        int j0 = nBase + wn * 32 + nt * 8 + tig * 2;
        float bb0 = __ldg(&bias[j0]);
        float bb1 = __ldg(&bias[j0 + 1]);
#pragma unroll
        for (int mt = 0; mt < 4; mt++) {
            int m0 = mBase + wm * 64 + mt * 16 + grp;
            st_xwt(m0,     j0,     acc[mt][nt][0] + bb0);
            st_xwt(m0,     j0 + 1, acc[mt][nt][1] + bb1);
            st_xwt(m0 + 8, j0,     acc[mt][nt][2] + bb0);
            st_xwt(m0 + 8, j0 + 1, acc[mt][nt][3] + bb1);
        }
    }
}

// ---------------------------------------------------------------------------
__device__ __forceinline__ float sigf(float x) {
    return 1.0f / (1.0f + __expf(-x));
}
__device__ __forceinline__ float tanhfast(float x) {
    float e = __expf(2.0f * x);
    return 1.0f - 2.0f / (e + 1.0f);
}

// ---------------------------------------------------------------------------
// HMMA persistent scan, dataflow-synchronized (R12, proven best).
// ---------------------------------------------------------------------------
#define HROW 1040
#define HBUF (16 * HROW)                    // 16,640
#define BUF2 (2 * HBUF)                     // hi+lo for one parity: 33,280
#define SD_OFF (2 * BUF2)                   // 66,560
#define SDS 68
#define CSH_OFF (SD_OFF + 8 * 16 * SDS * 4) // 101,376
#define SMEM_SCAN (CSH_OFF + 1024)          // 102,400

__global__ __launch_bounds__(512, 1) void lstm_scan_kernel(
    const float* __restrict__ c0, const float* __restrict__ h0,
    float* __restrict__ out)
{
    extern __shared__ __align__(16) char sm[];
    float* sD  = (float*)(sm + SD_OFF);
    float* csh = (float*)(sm + CSH_OFF);
    const uint32_t sbase = smem_u32(sm);

    const int bx = blockIdx.x;
    const int gu = bx >> 2;            // unit group 0..31 (16 units)
    const int bq = bx & 3;             // batch quarter 0..3 (16 batches)
    const int u_base = gu * 16;
    const int b_base = bq * 16;
    const int tid = threadIdx.x;
    const int lane = tid & 31;
    const int wid = tid >> 5;
    const int grp = lane >> 2;
    const int tig = lane & 3;
    const int nw = wid & 1;            // row half (32 gate rows)
    const int kq = wid >> 1;           // k slice (2x32 units)
    const int ab = tid >> 4;           // activation local batch 0..15 (tid<256)
    const int au = tid & 15;           // activation unit 0..15

    // ---- Wh B fragments -> registers (warp: 32 rows x 64 k) ----
    uint32_t bH[4][4][2], bL[4][4][2];
    {
        const __nv_bfloat16* baseH = g_whB_hi + (size_t)gu * 64 * 512;
        const __nv_bfloat16* baseL = g_whB_lo + (size_t)gu * 64 * 512;
#pragma unroll
        for (int ks = 0; ks < 4; ks++) {
            int kf = (ks < 2) ? (kq * 32 + ks * 16) : (256 + kq * 32 + (ks - 2) * 16);
            kf += tig * 2;
#pragma unroll
            for (int nt = 0; nt < 4; nt++) {
                int r = nw * 32 + nt * 8 + grp;
                bH[ks][nt][0] = *(const uint32_t*)(baseH + (size_t)r * 512 + kf);
                bH[ks][nt][1] = *(const uint32_t*)(baseH + (size_t)r * 512 + kf + 8);
                bL[ks][nt][0] = *(const uint32_t*)(baseL + (size_t)r * 512 + kf);
                bL[ks][nt][1] = *(const uint32_t*)(baseL + (size_t)r * 512 + kf + 8);
            }
        }
    }

    if (tid < 256) {
        int bg = b_base + ab;
        csh[tid] = c0[bg * HH + u_base + au];
        float hv = h0[bg * HH + u_base + au];
        __nv_bfloat16 hi = __float2bfloat16(hv);
        __nv_bfloat16 lo = __float2bfloat16(hv - __bfloat162float(hi));
        g_hb_hi[0][bg * HH + u_base + au] = hi;
        g_hb_lo[0][bg * HH + u_base + au] = lo;
    }
    __syncthreads();
    if (tid == 0) {
        __threadfence();
        st_rel(&g_pflag[bq][gu * 32], 1u);    // production #0 (init) done
    }

    float* ys = out + 2 * BATCH * HH;

    for (int s = 0; s < TT; s++) {
        const int ph = s & 1;

        float4 xw = make_float4(0.f, 0.f, 0.f, 0.f);
        if (tid < 256)
            xw = __ldg((const float4*)g_xwt +
                       ((((size_t)s * 32 + gu) * 64 + b_base + ab) * 16 + au));

        // ---- loader warp: poll 4 producers, fetch 4KB slice ----
        if (nw == 0) {
            if (lane < 4) {
                int pg = 2 * kq + (lane & 1) + ((lane >> 1) << 4);
                const unsigned* f = &g_pflag[bq][pg * 32];
                while (ld_acq(f) < (unsigned)(s + 1)) __nanosleep(20);
            }
            __syncwarp();
            const char* srcH = (const char*)g_hb_hi[ph];
            const char* srcL = (const char*)g_hb_lo[ph];
            uint32_t dbase = sbase + (s & 1) * BUF2;
#pragma unroll
            for (int q = 0; q < 8; q++) {
                int idx = q * 32 + lane;      // 0..255
                int row = idx & 15;
                int rest = idx >> 4;          // 0..15
                int hl = rest & 1;
                int half = (rest >> 1) & 1;
                int seg = rest >> 2;          // 0..3
                uint32_t off = row * HROW + half * 512 + kq * 64 + seg * 16;
                size_t src = (size_t)(b_base + row) * 1024 + half * 512 + kq * 64 + seg * 16;
                CP_ASYNC16(dbase + hl * HBUF + off, (hl ? srcL : srcH) + src);
            }
            CP_COMMIT();
            CP_WAIT(0);
        }
        // pair barrier: loader's smem writes visible to partner warp
        asm volatile("bar.sync %0, %1;" :: "r"(kq + 1), "r"(64) : "memory");

        float acc[4][4];   // [nt][q]
#pragma unroll
        for (int nt = 0; nt < 4; nt++)
#pragma unroll
            for (int q = 0; q < 4; q++) acc[nt][q] = 0.f;

        const char* bufH = sm + (s & 1) * BUF2;
        const char* bufL = bufH + HBUF;

#pragma unroll
        for (int ks = 0; ks < 4; ks++) {
            int col = (ks < 2) ? ((kq * 32 + ks * 16 + tig * 2) * 2)
                               : ((256 + kq * 32 + (ks - 2) * 16 + tig * 2) * 2);
            int aoff = grp * HROW + col;
            uint32_t ah0 = *(const uint32_t*)(bufH + aoff);
            uint32_t ah1 = *(const uint32_t*)(bufH + aoff + 8 * HROW);
            uint32_t ah2 = *(const uint32_t*)(bufH + aoff + 16);
            uint32_t ah3 = *(const uint32_t*)(bufH + aoff + 8 * HROW + 16);
            uint32_t al0 = *(const uint32_t*)(bufL + aoff);
            uint32_t al1 = *(const uint32_t*)(bufL + aoff + 8 * HROW);
            uint32_t al2 = *(const uint32_t*)(bufL + aoff + 16);
            uint32_t al3 = *(const uint32_t*)(bufL + aoff + 8 * HROW + 16);
#pragma unroll
            for (int nt = 0; nt < 4; nt++) {
                MMA_BF16(acc[nt], ah0, ah1, ah2, ah3, bH[ks][nt][0], bH[ks][nt][1]);
                MMA_BF16(acc[nt], al0, al1, al2, al3, bH[ks][nt][0], bH[ks][nt][1]);
                MMA_BF16(acc[nt], ah0, ah1, ah2, ah3, bL[ks][nt][0], bL[ks][nt][1]);
            }
        }

        // store D partials: sD[kq][b 16][r 64]
#pragma unroll
        for (int nt = 0; nt < 4; nt++) {
            int r = nw * 32 + nt * 8 + tig * 2;
            *(float2*)&sD[(kq * 16 + grp) * SDS + r] =
                make_float2(acc[nt][0], acc[nt][1]);
            *(float2*)&sD[(kq * 16 + grp + 8) * SDS + r] =
                make_float2(acc[nt][2], acc[nt][3]);
        }
        __syncthreads();

        if (tid < 256) {
            float si = xw.x, sf = xw.y, sg2 = xw.z, so = xw.w;
#pragma unroll
            for (int q = 0; q < 8; q++) {
                float4 s4 = *(float4*)&sD[(q * 16 + ab) * SDS + au * 4];
                si += s4.x; sf += s4.y; sg2 += s4.z; so += s4.w;
            }
            float ig = sigf(si);
            float fg = sigf(sf);
            float gg = tanhfast(sg2);
            float og = sigf(so);
            float cold = csh[tid];
            float cnew = fg * cold + ig * gg;
            float hnew = og * tanhfast(cnew);
            csh[tid] = cnew;

            int bg = b_base + ab;
            __nv_bfloat16 hi = __float2bfloat16(hnew);
            __nv_bfloat16 lo = __float2bfloat16(hnew - __bfloat162float(hi));
            int uo = bg * HH + u_base + au;
            g_hb_hi[ph ^ 1][uo] = hi;
            g_hb_lo[ph ^ 1][uo] = lo;

            ys[((size_t)bg * TT + s) * HH + u_base + au] = hnew;
            if (s == TT - 1) {
                out[bg * HH + u_base + au] = cnew;                 // cT
                out[BATCH * HH + bg * HH + u_base + au] = hnew;    // hT
            }
        }
        __syncthreads();
        if (s < TT - 1 && tid == 0) {
            __threadfence();
            st_rel(&g_pflag[bq][gu * 32], (unsigned)(s + 2));
        }
    }
}

// ---------------------------------------------------------------------------
extern "C" void kernel_launch(void* const* d_in, const int* in_sizes, int n_in,
                              void* d_out, int out_size) {
    const float* x    = (const float*)d_in[0];   // [64][1024][512]
    const float* c0   = (const float*)d_in[1];   // [64][512]
    const float* h0   = (const float*)d_in[2];   // [64][512]
    const float* Wi   = (const float*)d_in[3];   // [512][2048]
    const float* Wh   = (const float*)d_in[4];   // [512][2048]
    const float* bias = (const float*)d_in[5];   // [2048]
    float* out = (float*)d_out;                  // cT | hT | ys

    cudaFuncSetAttribute(lstm_scan_kernel,
                         cudaFuncAttributeMaxDynamicSharedMemorySize, SMEM_SCAN);
    cudaFuncSetAttribute(gemm_hmma_kernel,
                         cudaFuncAttributeMaxDynamicSharedMemorySize, SMEM_GEMM);

    pack_x_kernel<<<131072, 256>>>(x);
    pack_wi_kernel<<<4096, 256>>>(Wi);
    pack_whB_kernel<<<4096, 256>>>(Wh);
    reset_bar_kernel<<<16, 256>>>();
    gemm_hmma_kernel<<<dim3(16, 512), 256, SMEM_GEMM>>>(bias);
    lstm_scan_kernel<<<GRID_R, 512, SMEM_SCAN>>>(c0, h0, out);
}

// round 15
// speedup vs baseline: 1.1289x; 1.0933x over previous
#include <cuda_runtime.h>
#include <cuda_bf16.h>
#include <cstdint>

#define BATCH 64
#define TT 1024
#define DD 512
#define HH 512
#define J4 2048
#define GRID_R 128        // scan grid (<=148 SMs -> co-resident)

// Scratch (static device memory; no runtime allocation)
__device__ float g_xwt[(size_t)TT * 32 * 64 * 64];    // [t][gu][b][ut][g]   512 MB
__device__ __nv_bfloat16 g_xb_hi[(size_t)BATCH * TT * DD];  // X bf16 hi [m][k]  64 MB
__device__ __nv_bfloat16 g_xb_lo[(size_t)BATCH * TT * DD];  // X bf16 lo [m][k]  64 MB
__device__ __nv_bfloat16 g_wib_hi[(size_t)J4 * DD];   // [n][k] bf16 hi      2 MB
__device__ __nv_bfloat16 g_wib_lo[(size_t)J4 * DD];   // [n][k] bf16 lo      2 MB
__device__ __nv_bfloat16 g_whB_hi[(size_t)32 * 64 * 512];   // [gu][r][k]    2 MB
__device__ __nv_bfloat16 g_whB_lo[(size_t)32 * 64 * 512];   // [gu][r][k]    2 MB
__device__ __nv_bfloat16 g_hb_hi[2][BATCH * HH];      // h bf16 hi, [b][u]
__device__ __nv_bfloat16 g_hb_lo[2][BATCH * HH];      // h bf16 lo, [b][u]
__device__ unsigned g_pflag[4][32 * 32];              // [bq][gu*32] production count

// ---------------------------------------------------------------------------
__device__ __forceinline__ uint32_t smem_u32(const void* p) {
    uint32_t a;
    asm("{ .reg .u64 t; cvta.to.shared.u64 t, %1; cvt.u32.u64 %0, t; }"
        : "=r"(a) : "l"(p));
    return a;
}
#define CP_ASYNC16(dst, src) \
    asm volatile("cp.async.cg.shared.global [%0], [%1], 16;" :: "r"(dst), "l"(src))
#define CP_COMMIT()  asm volatile("cp.async.commit_group;" ::: "memory")
#define CP_WAIT(n)   asm volatile("cp.async.wait_group %0;" :: "n"(n) : "memory")

#define MMA_BF16(d, a0, a1, a2, a3, b0, b1)                                    \
    asm volatile("mma.sync.aligned.m16n8k16.row.col.f32.bf16.bf16.f32 "        \
                 "{%0,%1,%2,%3},{%4,%5,%6,%7},{%8,%9},{%0,%1,%2,%3};"          \
                 : "+f"((d)[0]), "+f"((d)[1]), "+f"((d)[2]), "+f"((d)[3])      \
                 : "r"(a0), "r"(a1), "r"(a2), "r"(a3), "r"(b0), "r"(b1))

#define LDSM_X4(r0, r1, r2, r3, addr)                                          \
    asm volatile("ldmatrix.sync.aligned.m8n8.x4.shared.b16 {%0,%1,%2,%3}, [%4];" \
                 : "=r"(r0), "=r"(r1), "=r"(r2), "=r"(r3) : "r"(addr))

__device__ __forceinline__ void st_rel(unsigned* p, unsigned v) {
    asm volatile("st.release.gpu.u32 [%0], %1;" :: "l"(p), "r"(v) : "memory");
}
__device__ __forceinline__ unsigned ld_acq(const unsigned* p) {
    unsigned v;
    asm volatile("ld.acquire.gpu.u32 %0, [%1];" : "=r"(v) : "l"(p) : "memory");
    return v;
}

// ---------------------------------------------------------------------------
__global__ void reset_bar_kernel() {
    ((unsigned*)g_pflag)[blockIdx.x * 256 + threadIdx.x] = 0u;
}

// X fp32 -> bf16 hi/lo split (same [m][k] layout)
__global__ void pack_x_kernel(const float* __restrict__ X) {
    size_t i = (size_t)blockIdx.x * 256 + threadIdx.x;
    float w = X[i];
    __nv_bfloat16 hi = __float2bfloat16(w);
    __nv_bfloat16 lo = __float2bfloat16(w - __bfloat162float(hi));
    g_xb_hi[i] = hi;
    g_xb_lo[i] = lo;
}

// Wi[k][n] -> bf16 hi/lo split, transposed [n][k]
__global__ void pack_wi_kernel(const float* __restrict__ Wi) {
    int i = blockIdx.x * 256 + threadIdx.x;
    int k = i & 511;
    int n = i >> 9;
    float w = Wi[(size_t)k * J4 + n];
    __nv_bfloat16 hi = __float2bfloat16(w);
    __nv_bfloat16 lo = __float2bfloat16(w - __bfloat162float(hi));
    g_wib_hi[i] = hi;
    g_wib_lo[i] = lo;
}

// Wh -> per-unit-group B rows: g_whB[gu][r=ut*4+g][k], gu has 16 units (64 rows)
__global__ void pack_whB_kernel(const float* __restrict__ Wh) {
    int i  = blockIdx.x * 256 + threadIdx.x;     // 1,048,576 total
    int k  = i & 511;
    int r  = (i >> 9) & 63;
    int gu = i >> 15;
    int ut = r >> 2, g = r & 3;
    float w = Wh[(size_t)k * J4 + g * 512 + gu * 16 + ut];
    __nv_bfloat16 hi = __float2bfloat16(w);
    __nv_bfloat16 lo = __float2bfloat16(w - __bfloat162float(hi));
    g_whB_hi[i] = hi;
    g_whB_lo[i] = lo;
}

// ---------------------------------------------------------------------------
// HMMA GEMM, cp.async double-buffered + LDSM fragment loads, 2 blocks/SM.
// 128x128xK512 (BK=32), 8 warps (2 wm x 4 wn), warp tile 64x32.
// ---------------------------------------------------------------------------
#define RSTRIDE 80
#define ARR_SZ (128 * RSTRIDE)     // 10240
#define BUFG_SZ (4 * ARR_SZ)       // 40960
#define SMEM_GEMM (2 * BUFG_SZ)    // 81920

// m = b*1024 + t ; j = g*512 + u  ->  g_xwt[t][gu][b][ut][g]
__device__ __forceinline__ void st_xwt(int m, int j, float v) {
    int b = m >> 10, t = m & 1023, u = j & 511, g = j >> 9;
    int gu = u >> 4, ut = u & 15;
    g_xwt[((((size_t)t * 32 + gu) * 64 + b) * 16 + ut) * 4 + g] = v;
}

__global__ __launch_bounds__(256, 2) void gemm_hmma_kernel(const float* __restrict__ bias)
{
    extern __shared__ __align__(16) char sm[];
    const uint32_t sbase = smem_u32(sm);

    const int nBase = blockIdx.x * 128;
    const int mBase = blockIdx.y * 128;
    const int tid = threadIdx.x;
    const int wid = tid >> 5;
    const int lane = tid & 31;
    const int wm = wid >> 2;
    const int wn = wid & 3;
    const int tig = lane & 3;
    const int grp = lane >> 2;

    // ldmatrix lane->address mappings
    const int lA = lane & 15;             // A row within 16-row tile
    const int cA = (lane >> 4) * 16;      // A col byte offset (k half)
    const int lB = lane & 7;              // B row within 8-row n-tile
    const int sB = ((lane >> 3) & 1) * 16;// B col byte offset (k half)
    const int nB = lane >> 4;             // B n-tile select within pair

    float acc[4][4][4];
#pragma unroll
    for (int mt = 0; mt < 4; mt++)
#pragma unroll
        for (int nt = 0; nt < 4; nt++)
#pragma unroll
            for (int q = 0; q < 4; q++) acc[mt][nt][q] = 0.f;

    const int s0 = tid * 2;

#define FILL_CHUNK(buf, ch) do {                                               \
    int k0 = (ch) * 32;                                                        \
    uint32_t db = sbase + (buf) * BUFG_SZ;                                     \
    _Pragma("unroll")                                                          \
    for (int q = 0; q < 2; q++) {                                              \
        int s2 = s0 + q;                                                       \
        int row = s2 >> 2, sg = s2 & 3;                                        \
        uint32_t doff = row * RSTRIDE + sg * 16;                               \
        size_t asrc = ((size_t)(mBase + row) * 512 + k0 + sg * 8) * 2;         \
        size_t bsrc = ((size_t)(nBase + row) * 512 + k0 + sg * 8) * 2;         \
        CP_ASYNC16(db + doff,              (const char*)g_xb_hi + asrc);       \
        CP_ASYNC16(db + ARR_SZ + doff,     (const char*)g_xb_lo + asrc);       \
        CP_ASYNC16(db + 2 * ARR_SZ + doff, (const char*)g_wib_hi + bsrc);      \
        CP_ASYNC16(db + 3 * ARR_SZ + doff, (const char*)g_wib_lo + bsrc);      \
    }                                                                          \
} while (0)

    FILL_CHUNK(0, 0);
    CP_COMMIT();

    for (int ch = 0; ch < 16; ch++) {
        if (ch < 15) {
            FILL_CHUNK((ch + 1) & 1, ch + 1);
            CP_COMMIT();
            CP_WAIT(1);
        } else {
            CP_WAIT(0);
        }
        __syncthreads();

        const uint32_t aBase = sbase + (ch & 1) * BUFG_SZ;   // AH base
        const uint32_t aBaseL = aBase + ARR_SZ;              // AL
        const uint32_t bBaseH = aBase + 2 * ARR_SZ;          // BH
        const uint32_t bBaseL = aBase + 3 * ARR_SZ;          // BL

#pragma unroll
        for (int ks = 0; ks < 2; ks++) {
            const int kb2 = ks * 32;   // byte offset of this k-half
            uint32_t bhf[4][2], blf[4][2];
#pragma unroll
            for (int ntp = 0; ntp < 2; ntp++) {
                int rowB = wn * 32 + (ntp * 2 + nB) * 8 + lB;
                uint32_t baddr = rowB * RSTRIDE + kb2 + sB;
                LDSM_X4(bhf[ntp * 2][0], bhf[ntp * 2][1],
                        bhf[ntp * 2 + 1][0], bhf[ntp * 2 + 1][1], bBaseH + baddr);
                LDSM_X4(blf[ntp * 2][0], blf[ntp * 2][1],
                        blf[ntp * 2 + 1][0], blf[ntp * 2 + 1][1], bBaseL + baddr);
            }
#pragma unroll
            for (int mt = 0; mt < 4; mt++) {
                int rowA = wm * 64 + mt * 16 + lA;
                uint32_t aaddr = rowA * RSTRIDE + kb2 + cA;
                uint32_t ah0, ah1, ah2, ah3, al0, al1, al2, al3;
                LDSM_X4(ah0, ah1, ah2, ah3, aBase + aaddr);
                LDSM_X4(al0, al1, al2, al3, aBaseL + aaddr);
#pragma unroll
                for (int nt = 0; nt < 4; nt++) {
                    MMA_BF16(acc[mt][nt], ah0, ah1, ah2, ah3, bhf[nt][0], bhf[nt][1]);
                    MMA_BF16(acc[mt][nt], al0, al1, al2, al3, bhf[nt][0], bhf[nt][1]);
                    MMA_BF16(acc[mt][nt], ah0, ah1, ah2, ah3, blf[nt][0], blf[nt][1]);
                }
            }
        }
        __syncthreads();
    }

#pragma unroll
    for (int nt = 0; nt < 4; nt++) {
        int j0 = nBase + wn * 32 + nt * 8 + tig * 2;
        float bb0 = __ldg(&bias[j0]);
        float bb1 = __ldg(&bias[j0 + 1]);
#pragma unroll
        for (int mt = 0; mt < 4; mt++) {
            int m0 = mBase + wm * 64 + mt * 16 + grp;
            st_xwt(m0,     j0,     acc[mt][nt][0] + bb0);
            st_xwt(m0,     j0 + 1, acc[mt][nt][1] + bb1);
            st_xwt(m0 + 8, j0,     acc[mt][nt][2] + bb0);
            st_xwt(m0 + 8, j0 + 1, acc[mt][nt][3] + bb1);
        }
    }
}

// ---------------------------------------------------------------------------
__device__ __forceinline__ float sigf(float x) {
    return 1.0f / (1.0f + __expf(-x));
}
__device__ __forceinline__ float tanhfast(float x) {
    float e = __expf(2.0f * x);
    return 1.0f - 2.0f / (e + 1.0f);
}

// ---------------------------------------------------------------------------
// HMMA persistent scan, dataflow-synchronized (R12 structure) + LDSM A-frags
// + trimmed producer critical path (no redundant fence; ys after flag).
// ---------------------------------------------------------------------------
#define HROW 1040
#define HBUF (16 * HROW)                    // 16,640
#define BUF2 (2 * HBUF)                     // hi+lo for one parity: 33,280
#define SD_OFF (2 * BUF2)                   // 66,560
#define SDS 68
#define CSH_OFF (SD_OFF + 8 * 16 * SDS * 4) // 101,376
#define SMEM_SCAN (CSH_OFF + 1024)          // 102,400

__global__ __launch_bounds__(512, 1) void lstm_scan_kernel(
    const float* __restrict__ c0, const float* __restrict__ h0,
    float* __restrict__ out)
{
    extern __shared__ __align__(16) char sm[];
    float* sD  = (float*)(sm + SD_OFF);
    float* csh = (float*)(sm + CSH_OFF);
    const uint32_t sbase = smem_u32(sm);

    const int bx = blockIdx.x;
    const int gu = bx >> 2;            // unit group 0..31 (16 units)
    const int bq = bx & 3;             // batch quarter 0..3 (16 batches)
    const int u_base = gu * 16;
    const int b_base = bq * 16;
    const int tid = threadIdx.x;
    const int lane = tid & 31;
    const int wid = tid >> 5;
    const int grp = lane >> 2;
    const int tig = lane & 3;
    const int nw = wid & 1;            // row half (32 gate rows)
    const int kq = wid >> 1;           // k slice (2x32 units)
    const int ab = tid >> 4;           // activation local batch 0..15 (tid<256)
    const int au = tid & 15;           // activation unit 0..15

    // ldmatrix A lane mapping (verified in GEMM): row = lane&15, k-half = lane>>4
    const int lA = lane & 15;
    const int cA = (lane >> 4) * 16;

    // ---- Wh B fragments -> registers (warp: 32 rows x 64 k) ----
    uint32_t bH[4][4][2], bL[4][4][2];
    {
        const __nv_bfloat16* baseH = g_whB_hi + (size_t)gu * 64 * 512;
        const __nv_bfloat16* baseL = g_whB_lo + (size_t)gu * 64 * 512;
#pragma unroll
        for (int ks = 0; ks < 4; ks++) {
            int kf = (ks < 2) ? (kq * 32 + ks * 16) : (256 + kq * 32 + (ks - 2) * 16);
            kf += tig * 2;
#pragma unroll
            for (int nt = 0; nt < 4; nt++) {
                int r = nw * 32 + nt * 8 + grp;
                bH[ks][nt][0] = *(const uint32_t*)(baseH + (size_t)r * 512 + kf);
                bH[ks][nt][1] = *(const uint32_t*)(baseH + (size_t)r * 512 + kf + 8);
                bL[ks][nt][0] = *(const uint32_t*)(baseL + (size_t)r * 512 + kf);
                bL[ks][nt][1] = *(const uint32_t*)(baseL + (size_t)r * 512 + kf + 8);
            }
        }
    }

    if (tid < 256) {
        int bg = b_base + ab;
        csh[tid] = c0[bg * HH + u_base + au];
        float hv = h0[bg * HH + u_base + au];
        __nv_bfloat16 hi = __float2bfloat16(hv);
        __nv_bfloat16 lo = __float2bfloat16(hv - __bfloat162float(hi));
        g_hb_hi[0][bg * HH + u_base + au] = hi;
        g_hb_lo[0][bg * HH + u_base + au] = lo;
    }
    __syncthreads();
    if (tid == 0) {
        st_rel(&g_pflag[bq][gu * 32], 1u);    // production #0 (init) done
    }

    float* ys = out + 2 * BATCH * HH;

    for (int s = 0; s < TT; s++) {
        const int ph = s & 1;

        float4 xw = make_float4(0.f, 0.f, 0.f, 0.f);
        if (tid < 256)
            xw = __ldg((const float4*)g_xwt +
                       ((((size_t)s * 32 + gu) * 64 + b_base + ab) * 16 + au));

        // ---- loader warp: poll 4 producers, fetch 4KB slice ----
        if (nw == 0) {
            if (lane < 4) {
                int pg = 2 * kq + (lane & 1) + ((lane >> 1) << 4);
                const unsigned* f = &g_pflag[bq][pg * 32];
                while (ld_acq(f) < (unsigned)(s + 1)) __nanosleep(20);
            }
            __syncwarp();
            const char* srcH = (const char*)g_hb_hi[ph];
            const char* srcL = (const char*)g_hb_lo[ph];
            uint32_t dbase = sbase + (s & 1) * BUF2;
#pragma unroll
            for (int q = 0; q < 8; q++) {
                int idx = q * 32 + lane;      // 0..255
                int row = idx & 15;
                int rest = idx >> 4;          // 0..15
                int hl = rest & 1;
                int half = (rest >> 1) & 1;
                int seg = rest >> 2;          // 0..3
                uint32_t off = row * HROW + half * 512 + kq * 64 + seg * 16;
                size_t src = (size_t)(b_base + row) * 1024 + half * 512 + kq * 64 + seg * 16;
                CP_ASYNC16(dbase + hl * HBUF + off, (hl ? srcL : srcH) + src);
            }
            CP_COMMIT();
            CP_WAIT(0);
        }
        // pair barrier: loader's smem writes visible to partner warp
        asm volatile("bar.sync %0, %1;" :: "r"(kq + 1), "r"(64) : "memory");

        float acc[4][4];   // [nt][q]
#pragma unroll
        for (int nt = 0; nt < 4; nt++)
#pragma unroll
            for (int q = 0; q < 4; q++) acc[nt][q] = 0.f;

        const uint32_t bufH = sbase + (s & 1) * BUF2;
        const uint32_t bufL = bufH + HBUF;

#pragma unroll
        for (int ks = 0; ks < 4; ks++) {
            int colb = (ks < 2) ? ((kq * 32 + ks * 16) * 2)
                                : ((256 + kq * 32 + (ks - 2) * 16) * 2);
            uint32_t addr = lA * HROW + colb + cA;
            uint32_t ah0, ah1, ah2, ah3, al0, al1, al2, al3;
            LDSM_X4(ah0, ah1, ah2, ah3, bufH + addr);
            LDSM_X4(al0, al1, al2, al3, bufL + addr);
#pragma unroll
            for (int nt = 0; nt < 4; nt++) {
                MMA_BF16(acc[nt], ah0, ah1, ah2, ah3, bH[ks][nt][0], bH[ks][nt][1]);
                MMA_BF16(acc[nt], al0, al1, al2, al3, bH[ks][nt][0], bH[ks][nt][1]);
                MMA_BF16(acc[nt], ah0, ah1, ah2, ah3, bL[ks][nt][0], bL[ks][nt][1]);
            }
        }

        // store D partials: sD[kq][b 16][r 64]
#pragma unroll
        for (int nt = 0; nt < 4; nt++) {
            int r = nw * 32 + nt * 8 + tig * 2;
            *(float2*)&sD[(kq * 16 + grp) * SDS + r] =
                make_float2(acc[nt][0], acc[nt][1]);
            *(float2*)&sD[(kq * 16 + grp + 8) * SDS + r] =
                make_float2(acc[nt][2], acc[nt][3]);
        }
        __syncthreads();

        float cnew = 0.f, hnew = 0.f;
        if (tid < 256) {
            float si = xw.x, sf = xw.y, sg2 = xw.z, so = xw.w;
#pragma unroll
            for (int q = 0; q < 8; q++) {
                float4 s4 = *(float4*)&sD[(q * 16 + ab) * SDS + au * 4];
                si += s4.x; sf += s4.y; sg2 += s4.z; so += s4.w;
            }
            float ig = sigf(si);
            float fg = sigf(sf);
            float gg = tanhfast(sg2);
            float og = sigf(so);
            float cold = csh[tid];
            cnew = fg * cold + ig * gg;
            hnew = og * tanhfast(cnew);
            csh[tid] = cnew;

            int bg = b_base + ab;
            __nv_bfloat16 hi = __float2bfloat16(hnew);
            __nv_bfloat16 lo = __float2bfloat16(hnew - __bfloat162float(hi));
            int uo = bg * HH + u_base + au;
            g_hb_hi[ph ^ 1][uo] = hi;
            g_hb_lo[ph ^ 1][uo] = lo;
        }
        __syncthreads();
        if (s < TT - 1 && tid == 0) {
            st_rel(&g_pflag[bq][gu * 32], (unsigned)(s + 2));
        }
        // consumer-invisible outputs AFTER flag release (off critical path)
        if (tid < 256) {
            int bg = b_base + ab;
            ys[((size_t)bg * TT + s) * HH + u_base + au] = hnew;
            if (s == TT - 1) {
                out[bg * HH + u_base + au] = cnew;                 // cT
                out[BATCH * HH + bg * HH + u_base + au] = hnew;    // hT
            }
        }
    }
}

// ---------------------------------------------------------------------------
extern "C" void kernel_launch(void* const* d_in, const int* in_sizes, int n_in,
                              void* d_out, int out_size) {
    const float* x    = (const float*)d_in[0];   // [64][1024][512]
    const float* c0   = (const float*)d_in[1];   // [64][512]
    const float* h0   = (const float*)d_in[2];   // [64][512]
    const float* Wi   = (const float*)d_in[3];   // [512][2048]
    const float* Wh   = (const float*)d_in[4];   // [512][2048]
    const float* bias = (const float*)d_in[5];   // [2048]
    float* out = (float*)d_out;                  // cT | hT | ys

    cudaFuncSetAttribute(lstm_scan_kernel,
                         cudaFuncAttributeMaxDynamicSharedMemorySize, SMEM_SCAN);
    cudaFuncSetAttribute(gemm_hmma_kernel,
                         cudaFuncAttributeMaxDynamicSharedMemorySize, SMEM_GEMM);

    pack_x_kernel<<<131072, 256>>>(x);
    pack_wi_kernel<<<4096, 256>>>(Wi);
    pack_whB_kernel<<<4096, 256>>>(Wh);
    reset_bar_kernel<<<16, 256>>>();
    gemm_hmma_kernel<<<dim3(16, 512), 256, SMEM_GEMM>>>(bias);
    lstm_scan_kernel<<<GRID_R, 512, SMEM_SCAN>>>(c0, h0, out);
}

// round 16
// speedup vs baseline: 1.1623x; 1.0296x over previous
#include <cuda_runtime.h>
#include <cuda_bf16.h>
#include <cstdint>

#define BATCH 64
#define TT 1024
#define DD 512
#define HH 512
#define J4 2048
#define GRID_R 128        // scan grid (<=148 SMs -> co-resident)

// Scratch (static device memory; no runtime allocation)
__device__ float g_xwt[(size_t)TT * 4 * 64 * 512];    // [t][g][b][u]        512 MB
__device__ __nv_bfloat16 g_xb_hi[(size_t)BATCH * TT * DD];  // X bf16 hi [m][k]  64 MB
__device__ __nv_bfloat16 g_xb_lo[(size_t)BATCH * TT * DD];  // X bf16 lo [m][k]  64 MB
__device__ __nv_bfloat16 g_wib_hi[(size_t)J4 * DD];   // [n][k] bf16 hi      2 MB
__device__ __nv_bfloat16 g_wib_lo[(size_t)J4 * DD];   // [n][k] bf16 lo      2 MB
__device__ __nv_bfloat16 g_whB_hi[(size_t)32 * 64 * 512];   // [gu][r][k]    2 MB
__device__ __nv_bfloat16 g_whB_lo[(size_t)32 * 64 * 512];   // [gu][r][k]    2 MB
__device__ __nv_bfloat16 g_hb_hi[2][BATCH * HH];      // h bf16 hi, [b][u]
__device__ __nv_bfloat16 g_hb_lo[2][BATCH * HH];      // h bf16 lo, [b][u]
__device__ unsigned g_pflag[4][32 * 32];              // [bq][gu*32] production count

// ---------------------------------------------------------------------------
__device__ __forceinline__ uint32_t smem_u32(const void* p) {
    uint32_t a;
    asm("{ .reg .u64 t; cvta.to.shared.u64 t, %1; cvt.u32.u64 %0, t; }"
        : "=r"(a) : "l"(p));
    return a;
}
#define CP_ASYNC16(dst, src) \
    asm volatile("cp.async.cg.shared.global [%0], [%1], 16;" :: "r"(dst), "l"(src))
#define CP_COMMIT()  asm volatile("cp.async.commit_group;" ::: "memory")
#define CP_WAIT(n)   asm volatile("cp.async.wait_group %0;" :: "n"(n) : "memory")

#define MMA_BF16(d, a0, a1, a2, a3, b0, b1)                                    \
    asm volatile("mma.sync.aligned.m16n8k16.row.col.f32.bf16.bf16.f32 "        \
                 "{%0,%1,%2,%3},{%4,%5,%6,%7},{%8,%9},{%0,%1,%2,%3};"          \
                 : "+f"((d)[0]), "+f"((d)[1]), "+f"((d)[2]), "+f"((d)[3])      \
                 : "r"(a0), "r"(a1), "r"(a2), "r"(a3), "r"(b0), "r"(b1))

#define LDSM_X4(r0, r1, r2, r3, addr)                                          \
    asm volatile("ldmatrix.sync.aligned.m8n8.x4.shared.b16 {%0,%1,%2,%3}, [%4];" \
                 : "=r"(r0), "=r"(r1), "=r"(r2), "=r"(r3) : "r"(addr))

__device__ __forceinline__ void st_rel(unsigned* p, unsigned v) {
    asm volatile("st.release.gpu.u32 [%0], %1;" :: "l"(p), "r"(v) : "memory");
}
__device__ __forceinline__ unsigned ld_acq(const unsigned* p) {
    unsigned v;
    asm volatile("ld.acquire.gpu.u32 %0, [%1];" : "=r"(v) : "l"(p) : "memory");
    return v;
}

// ---------------------------------------------------------------------------
__global__ void reset_bar_kernel() {
    ((unsigned*)g_pflag)[blockIdx.x * 256 + threadIdx.x] = 0u;
}

// X fp32 -> bf16 hi/lo split (same [m][k] layout)
__global__ void pack_x_kernel(const float* __restrict__ X) {
    size_t i = (size_t)blockIdx.x * 256 + threadIdx.x;
    float w = X[i];
    __nv_bfloat16 hi = __float2bfloat16(w);
    __nv_bfloat16 lo = __float2bfloat16(w - __bfloat162float(hi));
    g_xb_hi[i] = hi;
    g_xb_lo[i] = lo;
}

// Wi[k][n] -> bf16 hi/lo split, transposed [n][k]
__global__ void pack_wi_kernel(const float* __restrict__ Wi) {
    int i = blockIdx.x * 256 + threadIdx.x;
    int k = i & 511;
    int n = i >> 9;
    float w = Wi[(size_t)k * J4 + n];
    __nv_bfloat16 hi = __float2bfloat16(w);
    __nv_bfloat16 lo = __float2bfloat16(w - __bfloat162float(hi));
    g_wib_hi[i] = hi;
    g_wib_lo[i] = lo;
}

// Wh -> per-unit-group B rows: g_whB[gu][r=ut*4+g][k], gu has 16 units (64 rows)
__global__ void pack_whB_kernel(const float* __restrict__ Wh) {
    int i  = blockIdx.x * 256 + threadIdx.x;     // 1,048,576 total
    int k  = i & 511;
    int r  = (i >> 9) & 63;
    int gu = i >> 15;
    int ut = r >> 2, g = r & 3;
    float w = Wh[(size_t)k * J4 + g * 512 + gu * 16 + ut];
    __nv_bfloat16 hi = __float2bfloat16(w);
    __nv_bfloat16 lo = __float2bfloat16(w - __bfloat162float(hi));
    g_whB_hi[i] = hi;
    g_whB_lo[i] = lo;
}

// ---------------------------------------------------------------------------
// HMMA GEMM, cp.async double-buffered + LDSM + smem-transposed epilogue.
// 128x128xK512 (BK=32), 8 warps (2 wm x 4 wn), warp tile 64x32, 2 blocks/SM.
// Block: b = mBase>>10 (one batch), t0 = mBase&1023 (128 t), g = nBase>>9,
// u0 = nBase&511 (128 u). Epilogue stages into smem then writes each t-row
// as one contiguous 512B burst into g_xwt[t][g][b][u].
// ---------------------------------------------------------------------------
#define RSTRIDE 80
#define ARR_SZ (128 * RSTRIDE)     // 10240
#define BUFG_SZ (4 * ARR_SZ)       // 40960
#define SMEM_GEMM (2 * BUFG_SZ)    // 81920
#define RS 132                     // epilogue stage row stride (floats)

__global__ __launch_bounds__(256, 2) void gemm_hmma_kernel(const float* __restrict__ bias)
{
    extern __shared__ __align__(16) char sm[];
    const uint32_t sbase = smem_u32(sm);

    const int nBase = blockIdx.x * 128;
    const int mBase = blockIdx.y * 128;
    const int tid = threadIdx.x;
    const int wid = tid >> 5;
    const int lane = tid & 31;
    const int wm = wid >> 2;
    const int wn = wid & 3;
    const int tig = lane & 3;
    const int grp = lane >> 2;

    // ldmatrix lane->address mappings
    const int lA = lane & 15;
    const int cA = (lane >> 4) * 16;
    const int lB = lane & 7;
    const int sB = ((lane >> 3) & 1) * 16;
    const int nB = lane >> 4;

    float acc[4][4][4];
#pragma unroll
    for (int mt = 0; mt < 4; mt++)
#pragma unroll
        for (int nt = 0; nt < 4; nt++)
#pragma unroll
            for (int q = 0; q < 4; q++) acc[mt][nt][q] = 0.f;

    const int s0 = tid * 2;

#define FILL_CHUNK(buf, ch) do {                                               \
    int k0 = (ch) * 32;                                                        \
    uint32_t db = sbase + (buf) * BUFG_SZ;                                     \
    _Pragma("unroll")                                                          \
    for (int q = 0; q < 2; q++) {                                              \
        int s2 = s0 + q;                                                       \
        int row = s2 >> 2, sg = s2 & 3;                                        \
        uint32_t doff = row * RSTRIDE + sg * 16;                               \
        size_t asrc = ((size_t)(mBase + row) * 512 + k0 + sg * 8) * 2;         \
        size_t bsrc = ((size_t)(nBase + row) * 512 + k0 + sg * 8) * 2;         \
        CP_ASYNC16(db + doff,              (const char*)g_xb_hi + asrc);       \
        CP_ASYNC16(db + ARR_SZ + doff,     (const char*)g_xb_lo + asrc);       \
        CP_ASYNC16(db + 2 * ARR_SZ + doff, (const char*)g_wib_hi + bsrc);      \
        CP_ASYNC16(db + 3 * ARR_SZ + doff, (const char*)g_wib_lo + bsrc);      \
    }                                                                          \
} while (0)

    FILL_CHUNK(0, 0);
    CP_COMMIT();

    for (int ch = 0; ch < 16; ch++) {
        if (ch < 15) {
            FILL_CHUNK((ch + 1) & 1, ch + 1);
            CP_COMMIT();
            CP_WAIT(1);
        } else {
            CP_WAIT(0);
        }
        __syncthreads();

        const uint32_t aBase = sbase + (ch & 1) * BUFG_SZ;
        const uint32_t aBaseL = aBase + ARR_SZ;
        const uint32_t bBaseH = aBase + 2 * ARR_SZ;
        const uint32_t bBaseL = aBase + 3 * ARR_SZ;

#pragma unroll
        for (int ks = 0; ks < 2; ks++) {
            const int kb2 = ks * 32;
            uint32_t bhf[4][2], blf[4][2];
#pragma unroll
            for (int ntp = 0; ntp < 2; ntp++) {
                int rowB = wn * 32 + (ntp * 2 + nB) * 8 + lB;
                uint32_t baddr = rowB * RSTRIDE + kb2 + sB;
                LDSM_X4(bhf[ntp * 2][0], bhf[ntp * 2][1],
                        bhf[ntp * 2 + 1][0], bhf[ntp * 2 + 1][1], bBaseH + baddr);
                LDSM_X4(blf[ntp * 2][0], blf[ntp * 2][1],
                        blf[ntp * 2 + 1][0], blf[ntp * 2 + 1][1], bBaseL + baddr);
            }
#pragma unroll
            for (int mt = 0; mt < 4; mt++) {
                int rowA = wm * 64 + mt * 16 + lA;
                uint32_t aaddr = rowA * RSTRIDE + kb2 + cA;
                uint32_t ah0, ah1, ah2, ah3, al0, al1, al2, al3;
                LDSM_X4(ah0, ah1, ah2, ah3, aBase + aaddr);
                LDSM_X4(al0, al1, al2, al3, aBaseL + aaddr);
#pragma unroll
                for (int nt = 0; nt < 4; nt++) {
                    MMA_BF16(acc[mt][nt], ah0, ah1, ah2, ah3, bhf[nt][0], bhf[nt][1]);
                    MMA_BF16(acc[mt][nt], al0, al1, al2, al3, bhf[nt][0], bhf[nt][1]);
                    MMA_BF16(acc[mt][nt], ah0, ah1, ah2, ah3, blf[nt][0], blf[nt][1]);
                }
            }
        }
        __syncthreads();
    }

    // ---- epilogue: stage to smem (f32, RS=132 pitch), then coalesced STG ----
    float* S = (float*)sm;   // 128 x 132 floats = 67,584 B (input buffers dead)
#pragma unroll
    for (int nt = 0; nt < 4; nt++) {
        int jl = wn * 32 + nt * 8 + tig * 2;
        float bb0 = __ldg(&bias[nBase + jl]);
        float bb1 = __ldg(&bias[nBase + jl + 1]);
#pragma unroll
        for (int mt = 0; mt < 4; mt++) {
            int r0 = wm * 64 + mt * 16 + grp;
            S[r0 * RS + jl]           = acc[mt][nt][0] + bb0;
            S[r0 * RS + jl + 1]       = acc[mt][nt][1] + bb1;
            S[(r0 + 8) * RS + jl]     = acc[mt][nt][2] + bb0;
            S[(r0 + 8) * RS + jl + 1] = acc[mt][nt][3] + bb1;
        }
    }
    __syncthreads();

    const int b  = mBase >> 10;
    const int t0 = mBase & 1023;
    const int g  = nBase >> 9;
    const int u0 = nBase & 511;
    const int r  = tid >> 1;               // row (local t) 0..127
    const int ch0 = (tid & 1) * 64;        // column half (floats)
    float* dst = g_xwt + ((((size_t)(t0 + r) * 4 + g) * 64 + b) * 512) + u0 + ch0;
    const float* srcS = S + r * RS + ch0;
#pragma unroll
    for (int q = 0; q < 16; q++) {
        float4 v = *(const float4*)(srcS + q * 4);
        *(float4*)(dst + q * 4) = v;
    }
}

// ---------------------------------------------------------------------------
__device__ __forceinline__ float sigf(float x) {
    return 1.0f / (1.0f + __expf(-x));
}
__device__ __forceinline__ float tanhfast(float x) {
    float e = __expf(2.0f * x);
    return 1.0f - 2.0f / (e + 1.0f);
}

// ---------------------------------------------------------------------------
// HMMA persistent scan, dataflow-synchronized + LDSM + split-wave h load:
// hi half committed first; hh MMAs start while lo half is still in flight.
// ---------------------------------------------------------------------------
#define HROW 1040
#define HBUF (16 * HROW)                    // 16,640
#define BUF2 (2 * HBUF)                     // hi+lo for one parity: 33,280
#define SD_OFF (2 * BUF2)                   // 66,560
#define SDS 68
#define CSH_OFF (SD_OFF + 8 * 16 * SDS * 4) // 101,376
#define SMEM_SCAN (CSH_OFF + 1024)          // 102,400

__global__ __launch_bounds__(512, 1) void lstm_scan_kernel(
    const float* __restrict__ c0, const float* __restrict__ h0,
    float* __restrict__ out)
{
    extern __shared__ __align__(16) char sm[];
    float* sD  = (float*)(sm + SD_OFF);
    float* csh = (float*)(sm + CSH_OFF);
    const uint32_t sbase = smem_u32(sm);

    const int bx = blockIdx.x;
    const int gu = bx >> 2;            // unit group 0..31 (16 units)
    const int bq = bx & 3;             // batch quarter 0..3 (16 batches)
    const int u_base = gu * 16;
    const int b_base = bq * 16;
    const int tid = threadIdx.x;
    const int lane = tid & 31;
    const int wid = tid >> 5;
    const int grp = lane >> 2;
    const int tig = lane & 3;
    const int nw = wid & 1;            // row half (32 gate rows)
    const int kq = wid >> 1;           // k slice (2x32 units)
    const int ab = tid >> 4;           // activation local batch 0..15 (tid<256)
    const int au = tid & 15;           // activation unit 0..15

    const int lA = lane & 15;
    const int cA = (lane >> 4) * 16;

    // ---- Wh B fragments -> registers (warp: 32 rows x 64 k) ----
    uint32_t bH[4][4][2], bL[4][4][2];
    {
        const __nv_bfloat16* baseH = g_whB_hi + (size_t)gu * 64 * 512;
        const __nv_bfloat16* baseL = g_whB_lo + (size_t)gu * 64 * 512;
#pragma unroll
        for (int ks = 0; ks < 4; ks++) {
            int kf = (ks < 2) ? (kq * 32 + ks * 16) : (256 + kq * 32 + (ks - 2) * 16);
            kf += tig * 2;
#pragma unroll
            for (int nt = 0; nt < 4; nt++) {
                int r = nw * 32 + nt * 8 + grp;
                bH[ks][nt][0] = *(const uint32_t*)(baseH + (size_t)r * 512 + kf);
                bH[ks][nt][1] = *(const uint32_t*)(baseH + (size_t)r * 512 + kf + 8);
                bL[ks][nt][0] = *(const uint32_t*)(baseL + (size_t)r * 512 + kf);
                bL[ks][nt][1] = *(const uint32_t*)(baseL + (size_t)r * 512 + kf + 8);
            }
        }
    }

    if (tid < 256) {
        int bg = b_base + ab;
        csh[tid] = c0[bg * HH + u_base + au];
        float hv = h0[bg * HH + u_base + au];
        __nv_bfloat16 hi = __float2bfloat16(hv);
        __nv_bfloat16 lo = __float2bfloat16(hv - __bfloat162float(hi));
        g_hb_hi[0][bg * HH + u_base + au] = hi;
        g_hb_lo[0][bg * HH + u_base + au] = lo;
    }
    __syncthreads();
    if (tid == 0) {
        st_rel(&g_pflag[bq][gu * 32], 1u);    // production #0 (init) done
    }

    float* ys = out + 2 * BATCH * HH;

    for (int s = 0; s < TT; s++) {
        const int ph = s & 1;

        float xwv[4] = {0.f, 0.f, 0.f, 0.f};
        if (tid < 256) {
            int bg = b_base + ab;
#pragma unroll
            for (int g = 0; g < 4; g++)
                xwv[g] = __ldg(&g_xwt[((((size_t)s * 4 + g) * 64 + bg) * 512) + u_base + au]);
        }

        // ---- loader warp: poll 4 producers, fetch hi wave then lo wave ----
        if (nw == 0) {
            if (lane < 4) {
                int pg = 2 * kq + (lane & 1) + ((lane >> 1) << 4);
                const unsigned* f = &g_pflag[bq][pg * 32];
                while (ld_acq(f) < (unsigned)(s + 1)) __nanosleep(20);
            }
            __syncwarp();
            const char* srcH = (const char*)g_hb_hi[ph];
            const char* srcL = (const char*)g_hb_lo[ph];
            uint32_t dbase = sbase + (s & 1) * BUF2;
#pragma unroll
            for (int q = 0; q < 4; q++) {        // hi wave: 128 segs
                int idx = q * 32 + lane;
                int row = idx & 15;
                int half = (idx >> 4) & 1;
                int seg = idx >> 5;
                uint32_t off = row * HROW + half * 512 + kq * 64 + seg * 16;
                size_t src = (size_t)(b_base + row) * 1024 + half * 512 + kq * 64 + seg * 16;
                CP_ASYNC16(dbase + off, srcH + src);
            }
            CP_COMMIT();
#pragma unroll
            for (int q = 0; q < 4; q++) {        // lo wave
                int idx = q * 32 + lane;
                int row = idx & 15;
                int half = (idx >> 4) & 1;
                int seg = idx >> 5;
                uint32_t off = row * HROW + half * 512 + kq * 64 + seg * 16;
                size_t src = (size_t)(b_base + row) * 1024 + half * 512 + kq * 64 + seg * 16;
                CP_ASYNC16(dbase + HBUF + off, srcL + src);
            }
            CP_COMMIT();
            CP_WAIT(1);      // hi landed
        }
        asm volatile("bar.sync %0, %1;" :: "r"(kq + 1), "r"(64) : "memory");

        float acc[4][4];
#pragma unroll
        for (int nt = 0; nt < 4; nt++)
#pragma unroll
            for (int q = 0; q < 4; q++) acc[nt][q] = 0.f;

        const uint32_t bufH = sbase + (s & 1) * BUF2;
        const uint32_t bufL = bufH + HBUF;

        // phase 1: hh MMAs (hi x Wh_hi); keep ah frags for phase 2
        uint32_t ahs[4][4];
#pragma unroll
        for (int ks = 0; ks < 4; ks++) {
            int colb = (ks < 2) ? ((kq * 32 + ks * 16) * 2)
                                : ((256 + kq * 32 + (ks - 2) * 16) * 2);
            uint32_t addr = lA * HROW + colb + cA;
            LDSM_X4(ahs[ks][0], ahs[ks][1], ahs[ks][2], ahs[ks][3], bufH + addr);
#pragma unroll
            for (int nt = 0; nt < 4; nt++)
                MMA_BF16(acc[nt], ahs[ks][0], ahs[ks][1], ahs[ks][2], ahs[ks][3],
                         bH[ks][nt][0], bH[ks][nt][1]);
        }
        if (nw == 0) CP_WAIT(0);     // lo landed
        asm volatile("bar.sync %0, %1;" :: "r"(kq + 1), "r"(64) : "memory");

        // phase 2: lh (lo x Wh_hi) + hl (hi x Wh_lo)
#pragma unroll
        for (int ks = 0; ks < 4; ks++) {
            int colb = (ks < 2) ? ((kq * 32 + ks * 16) * 2)
                                : ((256 + kq * 32 + (ks - 2) * 16) * 2);
            uint32_t addr = lA * HROW + colb + cA;
            uint32_t al0, al1, al2, al3;
            LDSM_X4(al0, al1, al2, al3, bufL + addr);
#pragma unroll
            for (int nt = 0; nt < 4; nt++) {
                MMA_BF16(acc[nt], al0, al1, al2, al3, bH[ks][nt][0], bH[ks][nt][1]);
                MMA_BF16(acc[nt], ahs[ks][0], ahs[ks][1], ahs[ks][2], ahs[ks][3],
                         bL[ks][nt][0], bL[ks][nt][1]);
            }
        }

        // store D partials: sD[kq][b 16][r 64]
#pragma unroll
        for (int nt = 0; nt < 4; nt++) {
            int r = nw * 32 + nt * 8 + tig * 2;
            *(float2*)&sD[(kq * 16 + grp) * SDS + r] =
                make_float2(acc[nt][0], acc[nt][1]);
            *(float2*)&sD[(kq * 16 + grp + 8) * SDS + r] =
                make_float2(acc[nt][2], acc[nt][3]);
        }
        __syncthreads();

        float cnew = 0.f, hnew = 0.f;
        if (tid < 256) {
            float si = xwv[0], sf = xwv[1], sg2 = xwv[2], so = xwv[3];
#pragma unroll
            for (int q = 0; q < 8; q++) {
                float4 s4 = *(float4*)&sD[(q * 16 + ab) * SDS + au * 4];
                si += s4.x; sf += s4.y; sg2 += s4.z; so += s4.w;
            }
            float ig = sigf(si);
            float fg = sigf(sf);
            float gg = tanhfast(sg2);
            float og = sigf(so);
            float cold = csh[tid];
            cnew = fg * cold + ig * gg;
            hnew = og * tanhfast(cnew);
            csh[tid] = cnew;

            int bg = b_base + ab;
            __nv_bfloat16 hi = __float2bfloat16(hnew);
            __nv_bfloat16 lo = __float2bfloat16(hnew - __bfloat162float(hi));
            int uo = bg * HH + u_base + au;
            g_hb_hi[ph ^ 1][uo] = hi;
            g_hb_lo[ph ^ 1][uo] = lo;
        }
        __syncthreads();
        if (s < TT - 1 && tid == 0) {
            st_rel(&g_pflag[bq][gu * 32], (unsigned)(s + 2));
        }
        // consumer-invisible outputs AFTER flag release (off critical path)
        if (tid < 256) {
            int bg = b_base + ab;
            ys[((size_t)bg * TT + s) * HH + u_base + au] = hnew;
            if (s == TT - 1) {
                out[bg * HH + u_base + au] = cnew;                 // cT
                out[BATCH * HH + bg * HH + u_base + au] = hnew;    // hT
            }
        }
    }
}

// ---------------------------------------------------------------------------
extern "C" void kernel_launch(void* const* d_in, const int* in_sizes, int n_in,
                              void* d_out, int out_size) {
    const float* x    = (const float*)d_in[0];   // [64][1024][512]
    const float* c0   = (const float*)d_in[1];   // [64][512]
    const float* h0   = (const float*)d_in[2];   // [64][512]
    const float* Wi   = (const float*)d_in[3];   // [512][2048]
    const float* Wh   = (const float*)d_in[4];   // [512][2048]
    const float* bias = (const float*)d_in[5];   // [2048]
    float* out = (float*)d_out;                  // cT | hT | ys

    cudaFuncSetAttribute(lstm_scan_kernel,
                         cudaFuncAttributeMaxDynamicSharedMemorySize, SMEM_SCAN);
    cudaFuncSetAttribute(gemm_hmma_kernel,
                         cudaFuncAttributeMaxDynamicSharedMemorySize, SMEM_GEMM);

    pack_x_kernel<<<131072, 256>>>(x);
    pack_wi_kernel<<<4096, 256>>>(Wi);
    pack_whB_kernel<<<4096, 256>>>(Wh);
    reset_bar_kernel<<<16, 256>>>();
    gemm_hmma_kernel<<<dim3(16, 512), 256, SMEM_GEMM>>>(bias);
    lstm_scan_kernel<<<GRID_R, 512, SMEM_SCAN>>>(c0, h0, out);
}

// round 17
// speedup vs baseline: 1.1836x; 1.0183x over previous
#include <cuda_runtime.h>
#include <cuda_bf16.h>
#include <cstdint>

#define BATCH 64
#define TT 1024
#define DD 512
#define HH 512
#define J4 2048
#define GRID_R 128        // scan grid (<=148 SMs -> co-resident)

// Scratch (static device memory; no runtime allocation)
__device__ float g_xwt[(size_t)TT * 4 * 64 * 512];    // [t][g][b][u]        512 MB
__device__ __nv_bfloat16 g_xb_hi[(size_t)BATCH * TT * DD];  // X bf16 hi [m][k]  64 MB
__device__ __nv_bfloat16 g_xb_lo[(size_t)BATCH * TT * DD];  // X bf16 lo [m][k]  64 MB
__device__ __nv_bfloat16 g_wib_hi[(size_t)J4 * DD];   // [n][k] bf16 hi      2 MB
__device__ __nv_bfloat16 g_wib_lo[(size_t)J4 * DD];   // [n][k] bf16 lo      2 MB
__device__ __nv_bfloat16 g_whB_hi[(size_t)32 * 64 * 512];   // [gu][r][k]    2 MB
__device__ __nv_bfloat16 g_whB_lo[(size_t)32 * 64 * 512];   // [gu][r][k]    2 MB
__device__ __nv_bfloat16 g_hb_hi[2][BATCH * HH];      // h bf16 hi, [b][u]
__device__ __nv_bfloat16 g_hb_lo[2][BATCH * HH];      // h bf16 lo, [b][u]
__device__ unsigned g_pflag[4][32 * 32];              // [bq][gu*32] production count

// ---------------------------------------------------------------------------
__device__ __forceinline__ uint32_t smem_u32(const void* p) {
    uint32_t a;
    asm("{ .reg .u64 t; cvta.to.shared.u64 t, %1; cvt.u32.u64 %0, t; }"
        : "=r"(a) : "l"(p));
    return a;
}
#define CP_ASYNC16(dst, src) \
    asm volatile("cp.async.cg.shared.global [%0], [%1], 16;" :: "r"(dst), "l"(src))
#define CP_COMMIT()  asm volatile("cp.async.commit_group;" ::: "memory")
#define CP_WAIT(n)   asm volatile("cp.async.wait_group %0;" :: "n"(n) : "memory")

#define MMA_BF16(d, a0, a1, a2, a3, b0, b1)                                    \
    asm volatile("mma.sync.aligned.m16n8k16.row.col.f32.bf16.bf16.f32 "        \
                 "{%0,%1,%2,%3},{%4,%5,%6,%7},{%8,%9},{%0,%1,%2,%3};"          \
                 : "+f"((d)[0]), "+f"((d)[1]), "+f"((d)[2]), "+f"((d)[3])      \
                 : "r"(a0), "r"(a1), "r"(a2), "r"(a3), "r"(b0), "r"(b1))

#define LDSM_X4(r0, r1, r2, r3, addr)                                          \
    asm volatile("ldmatrix.sync.aligned.m8n8.x4.shared.b16 {%0,%1,%2,%3}, [%4];" \
                 : "=r"(r0), "=r"(r1), "=r"(r2), "=r"(r3) : "r"(addr))

__device__ __forceinline__ void st_rel(unsigned* p, unsigned v) {
    asm volatile("st.release.gpu.u32 [%0], %1;" :: "l"(p), "r"(v) : "memory");
}
__device__ __forceinline__ unsigned ld_acq(const unsigned* p) {
    unsigned v;
    asm volatile("ld.acquire.gpu.u32 %0, [%1];" : "=r"(v) : "l"(p) : "memory");
    return v;
}
// tight-spin wait: hard spin first, then backoff
__device__ __forceinline__ void wait_flag(const unsigned* f, unsigned target) {
    unsigned v = ld_acq(f);
    int spins = 0;
    while (v < target) {
        if (++spins > 64) __nanosleep(32);
        v = ld_acq(f);
    }
}

// ---------------------------------------------------------------------------
// X fp32 -> bf16 hi/lo split, vectorized (4 elems/thread)
__global__ void pack_x_kernel(const float4* __restrict__ X4) {
    size_t i = (size_t)blockIdx.x * 256 + threadIdx.x;
    float4 v = X4[i];
    float f[4] = {v.x, v.y, v.z, v.w};
    uint32_t h[2], l[2];
#pragma unroll
    for (int j = 0; j < 2; j++) {
        __nv_bfloat16 a = __float2bfloat16(f[2 * j]);
        __nv_bfloat16 b = __float2bfloat16(f[2 * j + 1]);
        __nv_bfloat16 ra = __float2bfloat16(f[2 * j] - __bfloat162float(a));
        __nv_bfloat16 rb = __float2bfloat16(f[2 * j + 1] - __bfloat162float(b));
        __nv_bfloat162 hv; hv.x = a;  hv.y = b;
        __nv_bfloat162 lv; lv.x = ra; lv.y = rb;
        h[j] = *(uint32_t*)&hv;
        l[j] = *(uint32_t*)&lv;
    }
    *(uint2*)(g_xb_hi + i * 4) = make_uint2(h[0], h[1]);
    *(uint2*)(g_xb_lo + i * 4) = make_uint2(l[0], l[1]);
}

// Wi[k][n] -> bf16 hi/lo split, transposed [n][k]; also resets flags.
__global__ void pack_wi_kernel(const float* __restrict__ Wi) {
    int i = blockIdx.x * 256 + threadIdx.x;
    if (i < 4096) ((unsigned*)g_pflag)[i] = 0u;     // fold reset
    int k = i & 511;
    int n = i >> 9;
    float w = Wi[(size_t)k * J4 + n];
    __nv_bfloat16 hi = __float2bfloat16(w);
    __nv_bfloat16 lo = __float2bfloat16(w - __bfloat162float(hi));
    g_wib_hi[i] = hi;
    g_wib_lo[i] = lo;
}

// Wh -> per-unit-group B rows: g_whB[gu][r=ut*4+g][k], gu has 16 units (64 rows)
__global__ void pack_whB_kernel(const float* __restrict__ Wh) {
    int i  = blockIdx.x * 256 + threadIdx.x;     // 1,048,576 total
    int k  = i & 511;
    int r  = (i >> 9) & 63;
    int gu = i >> 15;
    int ut = r >> 2, g = r & 3;
    float w = Wh[(size_t)k * J4 + g * 512 + gu * 16 + ut];
    __nv_bfloat16 hi = __float2bfloat16(w);
    __nv_bfloat16 lo = __float2bfloat16(w - __bfloat162float(hi));
    g_whB_hi[i] = hi;
    g_whB_lo[i] = lo;
}

// ---------------------------------------------------------------------------
// HMMA GEMM, cp.async double-buffered + LDSM + smem-transposed epilogue.
// (R16, proven.)
// ---------------------------------------------------------------------------
#define RSTRIDE 80
#define ARR_SZ (128 * RSTRIDE)     // 10240
#define BUFG_SZ (4 * ARR_SZ)       // 40960
#define SMEM_GEMM (2 * BUFG_SZ)    // 81920
#define RS 132                     // epilogue stage row stride (floats)

__global__ __launch_bounds__(256, 2) void gemm_hmma_kernel(const float* __restrict__ bias)
{
    extern __shared__ __align__(16) char sm[];
    const uint32_t sbase = smem_u32(sm);

    const int nBase = blockIdx.x * 128;
    const int mBase = blockIdx.y * 128;
    const int tid = threadIdx.x;
    const int wid = tid >> 5;
    const int lane = tid & 31;
    const int wm = wid >> 2;
    const int wn = wid & 3;
    const int tig = lane & 3;
    const int grp = lane >> 2;

    const int lA = lane & 15;
    const int cA = (lane >> 4) * 16;
    const int lB = lane & 7;
    const int sB = ((lane >> 3) & 1) * 16;
    const int nB = lane >> 4;

    float acc[4][4][4];
#pragma unroll
    for (int mt = 0; mt < 4; mt++)
#pragma unroll
        for (int nt = 0; nt < 4; nt++)
#pragma unroll
            for (int q = 0; q < 4; q++) acc[mt][nt][q] = 0.f;

    const int s0 = tid * 2;

#define FILL_CHUNK(buf, ch) do {                                               \
    int k0 = (ch) * 32;                                                        \
    uint32_t db = sbase + (buf) * BUFG_SZ;                                     \
    _Pragma("unroll")                                                          \
    for (int q = 0; q < 2; q++) {                                              \
        int s2 = s0 + q;                                                       \
        int row = s2 >> 2, sg = s2 & 3;                                        \
        uint32_t doff = row * RSTRIDE + sg * 16;                               \
        size_t asrc = ((size_t)(mBase + row) * 512 + k0 + sg * 8) * 2;         \
        size_t bsrc = ((size_t)(nBase + row) * 512 + k0 + sg * 8) * 2;         \
        CP_ASYNC16(db + doff,              (const char*)g_xb_hi + asrc);       \
        CP_ASYNC16(db + ARR_SZ + doff,     (const char*)g_xb_lo + asrc);       \
        CP_ASYNC16(db + 2 * ARR_SZ + doff, (const char*)g_wib_hi + bsrc);      \
        CP_ASYNC16(db + 3 * ARR_SZ + doff, (const char*)g_wib_lo + bsrc);      \
    }                                                                          \
} while (0)

    FILL_CHUNK(0, 0);
    CP_COMMIT();

    for (int ch = 0; ch < 16; ch++) {
        if (ch < 15) {
            FILL_CHUNK((ch + 1) & 1, ch + 1);
            CP_COMMIT();
            CP_WAIT(1);
        } else {
            CP_WAIT(0);
        }
        __syncthreads();

        const uint32_t aBase = sbase + (ch & 1) * BUFG_SZ;
        const uint32_t aBaseL = aBase + ARR_SZ;
        const uint32_t bBaseH = aBase + 2 * ARR_SZ;
        const uint32_t bBaseL = aBase + 3 * ARR_SZ;

#pragma unroll
        for (int ks = 0; ks < 2; ks++) {
            const int kb2 = ks * 32;
            uint32_t bhf[4][2], blf[4][2];
#pragma unroll
            for (int ntp = 0; ntp < 2; ntp++) {
                int rowB = wn * 32 + (ntp * 2 + nB) * 8 + lB;
                uint32_t baddr = rowB * RSTRIDE + kb2 + sB;
                LDSM_X4(bhf[ntp * 2][0], bhf[ntp * 2][1],
                        bhf[ntp * 2 + 1][0], bhf[ntp * 2 + 1][1], bBaseH + baddr);
                LDSM_X4(blf[ntp * 2][0], blf[ntp * 2][1],
                        blf[ntp * 2 + 1][0], blf[ntp * 2 + 1][1], bBaseL + baddr);
            }
#pragma unroll
            for (int mt = 0; mt < 4; mt++) {
                int rowA = wm * 64 + mt * 16 + lA;
                uint32_t aaddr = rowA * RSTRIDE + kb2 + cA;
                uint32_t ah0, ah1, ah2, ah3, al0, al1, al2, al3;
                LDSM_X4(ah0, ah1, ah2, ah3, aBase + aaddr);
                LDSM_X4(al0, al1, al2, al3, aBaseL + aaddr);
#pragma unroll
                for (int nt = 0; nt < 4; nt++) {
                    MMA_BF16(acc[mt][nt], ah0, ah1, ah2, ah3, bhf[nt][0], bhf[nt][1]);
                    MMA_BF16(acc[mt][nt], al0, al1, al2, al3, bhf[nt][0], bhf[nt][1]);
                    MMA_BF16(acc[mt][nt], ah0, ah1, ah2, ah3, blf[nt][0], blf[nt][1]);
                }
            }
        }
        __syncthreads();
    }

    // epilogue: stage to smem, then coalesced STG
    float* S = (float*)sm;
#pragma unroll
    for (int nt = 0; nt < 4; nt++) {
        int jl = wn * 32 + nt * 8 + tig * 2;
        float bb0 = __ldg(&bias[nBase + jl]);
        float bb1 = __ldg(&bias[nBase + jl + 1]);
#pragma unroll
        for (int mt = 0; mt < 4; mt++) {
            int r0 = wm * 64 + mt * 16 + grp;
            S[r0 * RS + jl]           = acc[mt][nt][0] + bb0;
            S[r0 * RS + jl + 1]       = acc[mt][nt][1] + bb1;
            S[(r0 + 8) * RS + jl]     = acc[mt][nt][2] + bb0;
            S[(r0 + 8) * RS + jl + 1] = acc[mt][nt][3] + bb1;
        }
    }
    __syncthreads();

    const int b  = mBase >> 10;
    const int t0 = mBase & 1023;
    const int g  = nBase >> 9;
    const int u0 = nBase & 511;
    const int r  = tid >> 1;
    const int ch0 = (tid & 1) * 64;
    float* dst = g_xwt + ((((size_t)(t0 + r) * 4 + g) * 64 + b) * 512) + u0 + ch0;
    const float* srcS = S + r * RS + ch0;
#pragma unroll
    for (int q = 0; q < 16; q++) {
        float4 v = *(const float4*)(srcS + q * 4);
        *(float4*)(dst + q * 4) = v;
    }
}

// ---------------------------------------------------------------------------
__device__ __forceinline__ float sigf(float x) {
    return 1.0f / (1.0f + __expf(-x));
}
__device__ __forceinline__ float tanhfast(float x) {
    float e = __expf(2.0f * x);
    return 1.0f - 2.0f / (e + 1.0f);
}

// ---------------------------------------------------------------------------
// HMMA persistent scan, dataflow-synchronized + LDSM + split-wave h load
// + sD parity double-buffer + 256-thread release barrier (warps 8-15 skip
// the trailing sync and may run one iteration ahead; barrier instances
// stay matched: each warp hits the one mid-step __syncthreads per iter).
// ---------------------------------------------------------------------------
#define HROW 1040
#define HBUF (16 * HROW)                    // 16,640
#define BUF2 (2 * HBUF)                     // hi+lo for one parity: 33,280
#define SD_OFF (2 * BUF2)                   // 66,560
#define SDS 68
#define SD_SZ (8 * 16 * SDS * 4)            // 34,816 per parity
#define CSH_OFF (SD_OFF + 2 * SD_SZ)        // 136,192
#define SMEM_SCAN (CSH_OFF + 1024)          // 137,216

__global__ __launch_bounds__(512, 1) void lstm_scan_kernel(
    const float* __restrict__ c0, const float* __restrict__ h0,
    float* __restrict__ out)
{
    extern __shared__ __align__(16) char sm[];
    float* csh = (float*)(sm + CSH_OFF);
    const uint32_t sbase = smem_u32(sm);

    const int bx = blockIdx.x;
    const int gu = bx >> 2;            // unit group 0..31 (16 units)
    const int bq = bx & 3;             // batch quarter 0..3 (16 batches)
    const int u_base = gu * 16;
    const int b_base = bq * 16;
    const int tid = threadIdx.x;
    const int lane = tid & 31;
    const int wid = tid >> 5;
    const int grp = lane >> 2;
    const int tig = lane & 3;
    const int nw = wid & 1;            // row half (32 gate rows)
    const int kq = wid >> 1;           // k slice (2x32 units)
    const int ab = tid >> 4;           // activation local batch 0..15 (tid<256)
    const int au = tid & 15;           // activation unit 0..15

    const int lA = lane & 15;
    const int cA = (lane >> 4) * 16;

    // ---- Wh B fragments -> registers (warp: 32 rows x 64 k) ----
    uint32_t bH[4][4][2], bL[4][4][2];
    {
        const __nv_bfloat16* baseH = g_whB_hi + (size_t)gu * 64 * 512;
        const __nv_bfloat16* baseL = g_whB_lo + (size_t)gu * 64 * 512;
#pragma unroll
        for (int ks = 0; ks < 4; ks++) {
            int kf = (ks < 2) ? (kq * 32 + ks * 16) : (256 + kq * 32 + (ks - 2) * 16);
            kf += tig * 2;
#pragma unroll
            for (int nt = 0; nt < 4; nt++) {
                int r = nw * 32 + nt * 8 + grp;
                bH[ks][nt][0] = *(const uint32_t*)(baseH + (size_t)r * 512 + kf);
                bH[ks][nt][1] = *(const uint32_t*)(baseH + (size_t)r * 512 + kf + 8);
                bL[ks][nt][0] = *(const uint32_t*)(baseL + (size_t)r * 512 + kf);
                bL[ks][nt][1] = *(const uint32_t*)(baseL + (size_t)r * 512 + kf + 8);
            }
        }
    }

    if (tid < 256) {
        int bg = b_base + ab;
        csh[tid] = c0[bg * HH + u_base + au];
        float hv = h0[bg * HH + u_base + au];
        __nv_bfloat16 hi = __float2bfloat16(hv);
        __nv_bfloat16 lo = __float2bfloat16(hv - __bfloat162float(hi));
        g_hb_hi[0][bg * HH + u_base + au] = hi;
        g_hb_lo[0][bg * HH + u_base + au] = lo;
    }
    __syncthreads();
    if (tid == 0) {
        st_rel(&g_pflag[bq][gu * 32], 1u);    // production #0 (init) done
    }

    float* ys = out + 2 * BATCH * HH;

    for (int s = 0; s < TT; s++) {
        const int ph = s & 1;

        float xwv[4] = {0.f, 0.f, 0.f, 0.f};
        if (tid < 256) {
            int bg = b_base + ab;
#pragma unroll
            for (int g = 0; g < 4; g++)
                xwv[g] = __ldg(&g_xwt[((((size_t)s * 4 + g) * 64 + bg) * 512) + u_base + au]);
        }

        // ---- loader warp: poll 4 producers, fetch hi wave then lo wave ----
        if (nw == 0) {
            if (lane < 4) {
                int pg = 2 * kq + (lane & 1) + ((lane >> 1) << 4);
                wait_flag(&g_pflag[bq][pg * 32], (unsigned)(s + 1));
            }
            __syncwarp();
            const char* srcH = (const char*)g_hb_hi[ph];
            const char* srcL = (const char*)g_hb_lo[ph];
            uint32_t dbase = sbase + (s & 1) * BUF2;
#pragma unroll
            for (int q = 0; q < 4; q++) {        // hi wave
                int idx = q * 32 + lane;
                int row = idx & 15;
                int half = (idx >> 4) & 1;
                int seg = idx >> 5;
                uint32_t off = row * HROW + half * 512 + kq * 64 + seg * 16;
                size_t src = (size_t)(b_base + row) * 1024 + half * 512 + kq * 64 + seg * 16;
                CP_ASYNC16(dbase + off, srcH + src);
            }
            CP_COMMIT();
#pragma unroll
            for (int q = 0; q < 4; q++) {        // lo wave
                int idx = q * 32 + lane;
                int row = idx & 15;
                int half = (idx >> 4) & 1;
                int seg = idx >> 5;
                uint32_t off = row * HROW + half * 512 + kq * 64 + seg * 16;
                size_t src = (size_t)(b_base + row) * 1024 + half * 512 + kq * 64 + seg * 16;
                CP_ASYNC16(dbase + HBUF + off, srcL + src);
            }
            CP_COMMIT();
            CP_WAIT(1);      // hi landed
        }
        asm volatile("bar.sync %0, %1;" :: "r"(kq + 1), "r"(64) : "memory");

        float acc[4][4];
#pragma unroll
        for (int nt = 0; nt < 4; nt++)
#pragma unroll
            for (int q = 0; q < 4; q++) acc[nt][q] = 0.f;

        const uint32_t bufH = sbase + (s & 1) * BUF2;
        const uint32_t bufL = bufH + HBUF;

        // phase 1: hh MMAs; keep ah frags
        uint32_t ahs[4][4];
#pragma unroll
        for (int ks = 0; ks < 4; ks++) {
            int colb = (ks < 2) ? ((kq * 32 + ks * 16) * 2)
                                : ((256 + kq * 32 + (ks - 2) * 16) * 2);
            uint32_t addr = lA * HROW + colb + cA;
            LDSM_X4(ahs[ks][0], ahs[ks][1], ahs[ks][2], ahs[ks][3], bufH + addr);
#pragma unroll
            for (int nt = 0; nt < 4; nt++)
                MMA_BF16(acc[nt], ahs[ks][0], ahs[ks][1], ahs[ks][2], ahs[ks][3],
                         bH[ks][nt][0], bH[ks][nt][1]);
        }
        if (nw == 0) CP_WAIT(0);     // lo landed
        asm volatile("bar.sync %0, %1;" :: "r"(kq + 1), "r"(64) : "memory");

        // phase 2: lh + hl
#pragma unroll
        for (int ks = 0; ks < 4; ks++) {
            int colb = (ks < 2) ? ((kq * 32 + ks * 16) * 2)
                                : ((256 + kq * 32 + (ks - 2) * 16) * 2);
            uint32_t addr = lA * HROW + colb + cA;
            uint32_t al0, al1, al2, al3;
            LDSM_X4(al0, al1, al2, al3, bufL + addr);
#pragma unroll
            for (int nt = 0; nt < 4; nt++) {
                MMA_BF16(acc[nt], al0, al1, al2, al3, bH[ks][nt][0], bH[ks][nt][1]);
                MMA_BF16(acc[nt], ahs[ks][0], ahs[ks][1], ahs[ks][2], ahs[ks][3],
                         bL[ks][nt][0], bL[ks][nt][1]);
            }
        }

        // store D partials into parity buffer: sD[kq][b 16][r 64]
        float* sD = (float*)(sm + SD_OFF + (s & 1) * SD_SZ);
#pragma unroll
        for (int nt = 0; nt < 4; nt++) {
            int r = nw * 32 + nt * 8 + tig * 2;
            *(float2*)&sD[(kq * 16 + grp) * SDS + r] =
                make_float2(acc[nt][0], acc[nt][1]);
            *(float2*)&sD[(kq * 16 + grp + 8) * SDS + r] =
                make_float2(acc[nt][2], acc[nt][3]);
        }
        __syncthreads();   // one block-wide barrier per iteration (matched)

        if (tid < 256) {
            float si = xwv[0], sf = xwv[1], sg2 = xwv[2], so = xwv[3];
#pragma unroll
            for (int q = 0; q < 8; q++) {
                float4 s4 = *(float4*)&sD[(q * 16 + ab) * SDS + au * 4];
                si += s4.x; sf += s4.y; sg2 += s4.z; so += s4.w;
            }
            float ig = sigf(si);
            float fg = sigf(sf);
            float gg = tanhfast(sg2);
            float og = sigf(so);
            float cold = csh[tid];
            float cnew = fg * cold + ig * gg;
            float hnew = og * tanhfast(cnew);
            csh[tid] = cnew;

            int bg = b_base + ab;
            __nv_bfloat16 hi = __float2bfloat16(hnew);
            __nv_bfloat16 lo = __float2bfloat16(hnew - __bfloat162float(hi));
            int uo = bg * HH + u_base + au;
            g_hb_hi[ph ^ 1][uo] = hi;
            g_hb_lo[ph ^ 1][uo] = lo;

            // release barrier over the 256 producing threads only
            asm volatile("bar.sync 10, 256;" ::: "memory");
            if (tid == 0 && s < TT - 1) {
                st_rel(&g_pflag[bq][gu * 32], (unsigned)(s + 2));
            }

            // consumer-invisible outputs AFTER flag release
            ys[((size_t)bg * TT + s) * HH + u_base + au] = hnew;
            if (s == TT - 1) {
                out[bg * HH + u_base + au] = cnew;                 // cT
                out[BATCH * HH + bg * HH + u_base + au] = hnew;    // hT
            }
        }
        // warps 8-15 fall through: may run one iteration ahead (sD parity +
        // h smem parity make this race-free; flags gate their loads).
    }
}

// ---------------------------------------------------------------------------
extern "C" void kernel_launch(void* const* d_in, const int* in_sizes, int n_in,
                              void* d_out, int out_size) {
    const float* x    = (const float*)d_in[0];   // [64][1024][512]
    const float* c0   = (const float*)d_in[1];   // [64][512]
    const float* h0   = (const float*)d_in[2];   // [64][512]
    const float* Wi   = (const float*)d_in[3];   // [512][2048]
    const float* Wh   = (const float*)d_in[4];   // [512][2048]
    const float* bias = (const float*)d_in[5];   // [2048]
    float* out = (float*)d_out;                  // cT | hT | ys

    cudaFuncSetAttribute(lstm_scan_kernel,
                         cudaFuncAttributeMaxDynamicSharedMemorySize, SMEM_SCAN);
    cudaFuncSetAttribute(gemm_hmma_kernel,
                         cudaFuncAttributeMaxDynamicSharedMemorySize, SMEM_GEMM);

    pack_x_kernel<<<32768, 256>>>((const float4*)x);
    pack_wi_kernel<<<4096, 256>>>(Wi);       // also resets flags
    pack_whB_kernel<<<4096, 256>>>(Wh);
    gemm_hmma_kernel<<<dim3(16, 512), 256, SMEM_GEMM>>>(bias);
    lstm_scan_kernel<<<GRID_R, 512, SMEM_SCAN>>>(c0, h0, out);
}